// round 1
// baseline (speedup 1.0000x reference)
#include <cuda_runtime.h>
#include <math.h>

static constexpr int L_ = 6, D_ = 1024, H_ = 16, F_ = 4096, S_ = 512, B_ = 16, P_ = 512;
static constexpr int DH_ = D_ / H_;          // 64
static constexpr int M_ = B_ * S_;           // 8192

// ---------------- scratch (device globals; no allocations allowed) ----------
__device__ float g_h[(size_t)M_ * D_];
__device__ float g_xn[(size_t)M_ * D_];
__device__ float g_q[(size_t)M_ * D_];
__device__ float g_k[(size_t)M_ * D_];
__device__ float g_v[(size_t)M_ * D_];
__device__ float g_ctx[(size_t)M_ * D_];
__device__ float g_out1[(size_t)M_ * D_];
__device__ float g_ffn1[(size_t)M_ * F_];

// ---------------- h = x + pe -------------------------------------------------
__global__ __launch_bounds__(256) void addpe_kernel(const float* __restrict__ x,
                                                    const float* __restrict__ pe,
                                                    float* __restrict__ h) {
    int i = blockIdx.x * 256 + threadIdx.x;
    h[i] = x[i] + pe[i & (S_ * D_ - 1)];   // S*D = 524288 (pow2); pe broadcast over batch
}

// ---------------- LayerNorm (one block per row of D=1024) -------------------
__global__ __launch_bounds__(256) void ln_kernel(const float* __restrict__ x,
                                                 const float* __restrict__ g,
                                                 const float* __restrict__ b,
                                                 float* __restrict__ y) {
    int row = blockIdx.x, tid = threadIdx.x;
    const float* xr = x + (size_t)row * D_;
    float4 f = *(const float4*)(xr + tid * 4);
    float s  = f.x + f.y + f.z + f.w;
    float ss = f.x * f.x + f.y * f.y + f.z * f.z + f.w * f.w;
#pragma unroll
    for (int o = 16; o > 0; o >>= 1) {
        s  += __shfl_xor_sync(0xffffffffu, s, o);
        ss += __shfl_xor_sync(0xffffffffu, ss, o);
    }
    __shared__ float rs[8], rss[8];
    if ((tid & 31) == 0) { rs[tid >> 5] = s; rss[tid >> 5] = ss; }
    __syncthreads();
    float ts = 0.f, tss = 0.f;
#pragma unroll
    for (int i = 0; i < 8; i++) { ts += rs[i]; tss += rss[i]; }
    float mean = ts * (1.0f / D_);
    float var  = tss * (1.0f / D_) - mean * mean;
    float r    = rsqrtf(var + 1e-6f);
    float4 g4 = *(const float4*)(g + tid * 4);
    float4 b4 = *(const float4*)(b + tid * 4);
    float4 o;
    o.x = (f.x - mean) * r * g4.x + b4.x;
    o.y = (f.y - mean) * r * g4.y + b4.y;
    o.z = (f.z - mean) * r * g4.z + b4.z;
    o.w = (f.w - mean) * r * g4.w + b4.w;
    *(float4*)(y + (size_t)row * D_ + tid * 4) = o;
}

// ---------------- generic SGEMM: C = act(A@W + bias) + r1 + r2 --------------
// A:[MM,KK] row-major, W:[KK,NN] row-major. Tile 64x64, BK=16, 256 thr, 4x4/thr.
// act: 0=none, 1=exact GELU. r1/r2 nullable residuals (same shape as C).
__global__ __launch_bounds__(256) void gemm_kernel(
    const float* __restrict__ A, const float* __restrict__ W,
    const float* __restrict__ bias, const float* __restrict__ r1,
    const float* __restrict__ r2, float* __restrict__ C,
    int NN, int KK, int act) {
    __shared__ float As[16][64];
    __shared__ float Bs[16][64];
    const int tx = threadIdx.x, ty = threadIdx.y;
    const int tid = ty * 16 + tx;
    const int rowBase = blockIdx.y * 64, colBase = blockIdx.x * 64;
    const int arow = tid >> 2,  acol = (tid & 3) << 2;
    const int brow = tid >> 4,  bcol = (tid & 15) << 2;
    const float* Aptr = A + (size_t)(rowBase + arow) * KK + acol;
    const float* Wptr = W + (size_t)brow * NN + colBase + bcol;
    float acc[4][4] = {};
    for (int k0 = 0; k0 < KK; k0 += 16) {
        float4 a4 = *(const float4*)(Aptr + k0);
        float4 b4 = *(const float4*)(Wptr + (size_t)k0 * NN);
        As[acol + 0][arow] = a4.x; As[acol + 1][arow] = a4.y;
        As[acol + 2][arow] = a4.z; As[acol + 3][arow] = a4.w;
        *(float4*)&Bs[brow][bcol] = b4;
        __syncthreads();
#pragma unroll
        for (int kk = 0; kk < 16; kk++) {
            float4 av = *(const float4*)&As[kk][ty << 2];
            float4 bv = *(const float4*)&Bs[kk][tx << 2];
            float a[4] = {av.x, av.y, av.z, av.w};
            float b[4] = {bv.x, bv.y, bv.z, bv.w};
#pragma unroll
            for (int i = 0; i < 4; i++)
#pragma unroll
                for (int j = 0; j < 4; j++) acc[i][j] += a[i] * b[j];
        }
        __syncthreads();
    }
    float4 bb = *(const float4*)(bias + colBase + (tx << 2));
    float bcols[4] = {bb.x, bb.y, bb.z, bb.w};
#pragma unroll
    for (int i = 0; i < 4; i++) {
        int r = rowBase + (ty << 2) + i;
        size_t base = (size_t)r * NN + colBase + (tx << 2);
        float vv[4];
#pragma unroll
        for (int j = 0; j < 4; j++) vv[j] = acc[i][j] + bcols[j];
        if (act == 1) {
#pragma unroll
            for (int j = 0; j < 4; j++) vv[j] = vv[j] * normcdff(vv[j]);
        }
        if (r1) {
            float4 q1 = *(const float4*)(r1 + base);
            vv[0] += q1.x; vv[1] += q1.y; vv[2] += q1.z; vv[3] += q1.w;
        }
        if (r2) {
            float4 q2 = *(const float4*)(r2 + base);
            vv[0] += q2.x; vv[1] += q2.y; vv[2] += q2.z; vv[3] += q2.w;
        }
        float4 ov = {vv[0], vv[1], vv[2], vv[3]};
        *(float4*)(C + base) = ov;
    }
}

// ---------------- attention: per (b, h, 32-query tile) ----------------------
static constexpr int QB = 32;
static constexpr int SCS = 516;   // scores stride pad (bank spread)
static constexpr int KVS = 65;    // k/v tile stride pad
static constexpr int ATTN_SMEM = (QB * SCS + QB * 64 + 64 * KVS) * 4;  // 90880 B

__global__ __launch_bounds__(256) void attn_kernel(
    const float* __restrict__ Q, const float* __restrict__ Kt,
    const float* __restrict__ Vt, const float* __restrict__ bias,
    float* __restrict__ Ctx) {
    extern __shared__ float sm[];
    float* sc = sm;                 // [QB][SCS]
    float* qs = sm + QB * SCS;      // [QB][64]
    float* kv = qs + QB * 64;       // [64][KVS]
    const int tid = threadIdx.x;
    const int q0 = blockIdx.x * QB, h = blockIdx.y, b = blockIdx.z;

    // load Q tile
    for (int i = tid; i < QB * 16; i += 256) {
        int r = i >> 4, c = (i & 15) << 2;
        *(float4*)&qs[r * 64 + c] =
            *(const float4*)&Q[(size_t)(b * S_ + q0 + r) * D_ + h * DH_ + c];
    }
    const int qi = tid >> 3, jr = tid & 7;

    // scores = QK^T * scale + bias
    for (int kb = 0; kb < S_; kb += 64) {
        __syncthreads();
        for (int i = tid; i < 64 * 16; i += 256) {
            int r = i >> 4, c = (i & 15) << 2;
            float4 f = *(const float4*)&Kt[(size_t)(b * S_ + kb + r) * D_ + h * DH_ + c];
            kv[r * KVS + c] = f.x; kv[r * KVS + c + 1] = f.y;
            kv[r * KVS + c + 2] = f.z; kv[r * KVS + c + 3] = f.w;
        }
        __syncthreads();
        float acc[8] = {};
#pragma unroll 8
        for (int dd = 0; dd < 64; dd++) {
            float qv = qs[qi * 64 + dd];
#pragma unroll
            for (int t = 0; t < 8; t++) acc[t] += qv * kv[(jr + 8 * t) * KVS + dd];
        }
#pragma unroll
        for (int t = 0; t < 8; t++) {
            int j = jr + 8 * t;
            int rel = (q0 + qi) - (kb + j) + (P_ - 1);
            sc[qi * SCS + kb + j] = acc[t] * 0.125f + __ldg(&bias[rel * H_ + h]);
        }
    }
    __syncthreads();

    // softmax: 8 warps x 4 rows
    {
        int w = tid >> 5, lane = tid & 31;
#pragma unroll
        for (int rr = 0; rr < QB / 8; rr++) {
            int r = w * (QB / 8) + rr;
            float m = -1e30f;
            for (int c = lane; c < S_; c += 32) m = fmaxf(m, sc[r * SCS + c]);
#pragma unroll
            for (int o = 16; o > 0; o >>= 1) m = fmaxf(m, __shfl_xor_sync(0xffffffffu, m, o));
            float sum = 0.f;
            for (int c = lane; c < S_; c += 32) {
                float e = expf(sc[r * SCS + c] - m);
                sc[r * SCS + c] = e;
                sum += e;
            }
#pragma unroll
            for (int o = 16; o > 0; o >>= 1) sum += __shfl_xor_sync(0xffffffffu, sum, o);
            float inv = 1.0f / sum;
            for (int c = lane; c < S_; c += 32) sc[r * SCS + c] *= inv;
        }
    }

    // ctx = aw @ V
    float cacc[8] = {};
    for (int kb = 0; kb < S_; kb += 64) {
        __syncthreads();
        for (int i = tid; i < 64 * 16; i += 256) {
            int r = i >> 4, c = (i & 15) << 2;
            float4 f = *(const float4*)&Vt[(size_t)(b * S_ + kb + r) * D_ + h * DH_ + c];
            kv[r * KVS + c] = f.x; kv[r * KVS + c + 1] = f.y;
            kv[r * KVS + c + 2] = f.z; kv[r * KVS + c + 3] = f.w;
        }
        __syncthreads();
#pragma unroll 8
        for (int j = 0; j < 64; j++) {
            float a = sc[qi * SCS + kb + j];
#pragma unroll
            for (int t = 0; t < 8; t++) cacc[t] += a * kv[j * KVS + jr + 8 * t];
        }
    }
#pragma unroll
    for (int t = 0; t < 8; t++)
        Ctx[(size_t)(b * S_ + q0 + qi) * D_ + h * DH_ + jr + 8 * t] = cacc[t];
}

// ---------------- launch ----------------------------------------------------
extern "C" void kernel_launch(void* const* d_in, const int* in_sizes, int n_in,
                              void* d_out, int out_size) {
    (void)in_sizes; (void)n_in; (void)out_size;
    const float* x    = (const float*)d_in[0];
    const float* pe   = (const float*)d_in[1];
    const float* wq   = (const float*)d_in[2];
    const float* bq   = (const float*)d_in[3];
    const float* wk   = (const float*)d_in[4];
    const float* bk   = (const float*)d_in[5];
    const float* wv   = (const float*)d_in[6];
    const float* bv   = (const float*)d_in[7];
    const float* wo   = (const float*)d_in[8];
    const float* bo   = (const float*)d_in[9];
    const float* bt   = (const float*)d_in[10];
    const float* w1   = (const float*)d_in[11];
    const float* b1   = (const float*)d_in[12];
    const float* w2   = (const float*)d_in[13];
    const float* b2   = (const float*)d_in[14];
    const float* ln1g = (const float*)d_in[15];
    const float* ln1b = (const float*)d_in[16];
    const float* ln2g = (const float*)d_in[17];
    const float* ln2b = (const float*)d_in[18];
    float* out = (float*)d_out;

    float *hb, *xn, *q, *k, *v, *ctx, *o1, *f1;
    cudaGetSymbolAddress((void**)&hb,  g_h);
    cudaGetSymbolAddress((void**)&xn,  g_xn);
    cudaGetSymbolAddress((void**)&q,   g_q);
    cudaGetSymbolAddress((void**)&k,   g_k);
    cudaGetSymbolAddress((void**)&v,   g_v);
    cudaGetSymbolAddress((void**)&ctx, g_ctx);
    cudaGetSymbolAddress((void**)&o1,  g_out1);
    cudaGetSymbolAddress((void**)&f1,  g_ffn1);

    cudaFuncSetAttribute(attn_kernel, cudaFuncAttributeMaxDynamicSharedMemorySize, ATTN_SMEM);

    dim3 thr2(16, 16);
    dim3 gD(D_ / 64, M_ / 64);   // N=1024 outputs
    dim3 gF(F_ / 64, M_ / 64);   // N=4096 outputs
    dim3 gAttn(S_ / QB, H_, B_);

    addpe_kernel<<<(M_ * D_) / 256, 256>>>(x, pe, hb);

    for (int l = 0; l < L_; l++) {
        size_t oDD = (size_t)l * D_ * D_;
        size_t oDF = (size_t)l * D_ * F_;
        size_t oD  = (size_t)l * D_;
        size_t oF  = (size_t)l * F_;

        ln_kernel<<<M_, 256>>>(hb, ln1g + oD, ln1b + oD, xn);
        gemm_kernel<<<gD, thr2>>>(xn, wq + oDD, bq + oD, nullptr, nullptr, q, D_, D_, 0);
        gemm_kernel<<<gD, thr2>>>(xn, wk + oDD, bk + oD, nullptr, nullptr, k, D_, D_, 0);
        gemm_kernel<<<gD, thr2>>>(xn, wv + oDD, bv + oD, nullptr, nullptr, v, D_, D_, 0);

        attn_kernel<<<gAttn, 256, ATTN_SMEM>>>(q, k, v, bt + (size_t)l * (2 * P_ - 1) * H_, ctx);

        // out1 = ctx @ wo + bo + h
        gemm_kernel<<<gD, thr2>>>(ctx, wo + oDD, bo + oD, hb, nullptr, o1, D_, D_, 0);

        ln_kernel<<<M_, 256>>>(o1, ln2g + oD, ln2b + oD, xn);
        // ffn1 = gelu(xn2 @ w1 + b1)
        gemm_kernel<<<gF, thr2>>>(xn, w1 + oDF, b1 + oF, nullptr, nullptr, f1, F_, D_, 1);
        // h_new = ffn1 @ w2 + b2 + out1 + h_old
        float* dst = (l == L_ - 1) ? out : hb;
        gemm_kernel<<<gD, thr2>>>(f1, w2 + oDF, b2 + oD, o1, hb, dst, D_, F_, 0);
    }
}

// round 2
// speedup vs baseline: 1.4322x; 1.4322x over previous
#include <cuda_runtime.h>
#include <math.h>

static constexpr int L_ = 6, D_ = 1024, H_ = 16, F_ = 4096, S_ = 512, B_ = 16, P_ = 512;
static constexpr int DH_ = D_ / H_;          // 64
static constexpr int M_ = B_ * S_;           // 8192

// ---------------- scratch (device globals; no allocations allowed) ----------
__device__ float g_h[(size_t)M_ * D_];
__device__ float g_xn[(size_t)M_ * D_];
__device__ float g_q[(size_t)M_ * D_];
__device__ float g_k[(size_t)M_ * D_];
__device__ float g_v[(size_t)M_ * D_];
__device__ float g_ctx[(size_t)M_ * D_];
__device__ float g_out1[(size_t)M_ * D_];
__device__ float g_ffn1[(size_t)M_ * F_];

// ---------------- packed f32x2 helpers (Blackwell FFMA2) --------------------
typedef unsigned long long ull;

__device__ __forceinline__ ull dup2(float a) {
    ull d;
    asm("mov.b64 %0, {%1, %1};" : "=l"(d) : "f"(a));
    return d;
}
__device__ __forceinline__ void ffma2(ull& acc, ull a, ull b) {
    asm("fma.rn.f32x2 %0, %1, %2, %0;" : "+l"(acc) : "l"(a), "l"(b));
}
__device__ __forceinline__ float2 unpack2(ull v) {
    float2 r;
    asm("mov.b64 {%0, %1}, %2;" : "=f"(r.x), "=f"(r.y) : "l"(v));
    return r;
}

// ---------------- h = x + pe -------------------------------------------------
__global__ __launch_bounds__(256) void addpe_kernel(const float* __restrict__ x,
                                                    const float* __restrict__ pe,
                                                    float* __restrict__ h) {
    int i = blockIdx.x * 256 + threadIdx.x;
    h[i] = x[i] + pe[i & (S_ * D_ - 1)];
}

// ---------------- LayerNorm (one block per row of D=1024) -------------------
__global__ __launch_bounds__(256) void ln_kernel(const float* __restrict__ x,
                                                 const float* __restrict__ g,
                                                 const float* __restrict__ b,
                                                 float* __restrict__ y) {
    int row = blockIdx.x, tid = threadIdx.x;
    const float* xr = x + (size_t)row * D_;
    float4 f = *(const float4*)(xr + tid * 4);
    float s  = f.x + f.y + f.z + f.w;
    float ss = f.x * f.x + f.y * f.y + f.z * f.z + f.w * f.w;
#pragma unroll
    for (int o = 16; o > 0; o >>= 1) {
        s  += __shfl_xor_sync(0xffffffffu, s, o);
        ss += __shfl_xor_sync(0xffffffffu, ss, o);
    }
    __shared__ float rs[8], rss[8];
    if ((tid & 31) == 0) { rs[tid >> 5] = s; rss[tid >> 5] = ss; }
    __syncthreads();
    float ts = 0.f, tss = 0.f;
#pragma unroll
    for (int i = 0; i < 8; i++) { ts += rs[i]; tss += rss[i]; }
    float mean = ts * (1.0f / D_);
    float var  = tss * (1.0f / D_) - mean * mean;
    float r    = rsqrtf(var + 1e-6f);
    float4 g4 = *(const float4*)(g + tid * 4);
    float4 b4 = *(const float4*)(b + tid * 4);
    float4 o;
    o.x = (f.x - mean) * r * g4.x + b4.x;
    o.y = (f.y - mean) * r * g4.y + b4.y;
    o.z = (f.z - mean) * r * g4.z + b4.z;
    o.w = (f.w - mean) * r * g4.w + b4.w;
    *(float4*)(y + (size_t)row * D_ + tid * 4) = o;
}

// ---------------- SGEMM 128x128x16, 8x8/thr, FFMA2, double-buffered ---------
// C = act(A@W + bias) + r1 + r2. A:[MM,KK] rm, W:[KK,NN] rm.
__global__ __launch_bounds__(256, 2) void gemm2_kernel(
    const float* __restrict__ A, const float* __restrict__ W,
    const float* __restrict__ bias, const float* __restrict__ r1,
    const float* __restrict__ r2, float* __restrict__ C,
    int NN, int KK, int act) {
    __shared__ float As[2][16][132];   // [buf][k][m] transposed, padded
    __shared__ float Bs[2][16][128];   // [buf][k][n]

    const int tid = threadIdx.x;
    const int tx = tid & 15, ty = tid >> 4;
    const int rowBase = blockIdx.y * 128, colBase = blockIdx.x * 128;

    // loader indices
    const int arow = tid >> 2;            // 0..63
    const int acol = (tid & 3) << 2;      // 0,4,8,12
    const int brow = tid >> 4;            // 0..15
    const int bcol = (tid & 15) << 2;     // 0..60

    const float* Aptr = A + (size_t)(rowBase + arow) * KK + acol;
    const float* Wptr = W + (size_t)brow * NN + colBase + bcol;

    ull acc[8][4];
#pragma unroll
    for (int i = 0; i < 8; i++)
#pragma unroll
        for (int j = 0; j < 4; j++) acc[i][j] = 0ull;

    // prologue: load tile 0
    float4 pa0 = *(const float4*)(Aptr);
    float4 pa1 = *(const float4*)(Aptr + (size_t)64 * KK);
    float4 pb0 = *(const float4*)(Wptr);
    float4 pb1 = *(const float4*)(Wptr + 64);

    As[0][acol + 0][arow] = pa0.x; As[0][acol + 1][arow] = pa0.y;
    As[0][acol + 2][arow] = pa0.z; As[0][acol + 3][arow] = pa0.w;
    As[0][acol + 0][arow + 64] = pa1.x; As[0][acol + 1][arow + 64] = pa1.y;
    As[0][acol + 2][arow + 64] = pa1.z; As[0][acol + 3][arow + 64] = pa1.w;
    *(float4*)&Bs[0][brow][bcol]      = pb0;
    *(float4*)&Bs[0][brow][bcol + 64] = pb1;
    __syncthreads();

    int buf = 0;
    for (int k0 = 0; k0 < KK; k0 += 16) {
        const bool hasNext = (k0 + 16) < KK;
        if (hasNext) {
            pa0 = *(const float4*)(Aptr + k0 + 16);
            pa1 = *(const float4*)(Aptr + (size_t)64 * KK + k0 + 16);
            pb0 = *(const float4*)(Wptr + (size_t)(k0 + 16) * NN);
            pb1 = *(const float4*)(Wptr + (size_t)(k0 + 16) * NN + 64);
        }
#pragma unroll
        for (int kk = 0; kk < 16; kk++) {
            float4 a0 = *(const float4*)&As[buf][kk][ty * 4];
            float4 a1 = *(const float4*)&As[buf][kk][ty * 4 + 64];
            ulonglong2 bq0 = *(const ulonglong2*)&Bs[buf][kk][tx * 4];
            ulonglong2 bq1 = *(const ulonglong2*)&Bs[buf][kk][tx * 4 + 64];
            ull b[4] = {bq0.x, bq0.y, bq1.x, bq1.y};
            ull ad[8] = {dup2(a0.x), dup2(a0.y), dup2(a0.z), dup2(a0.w),
                         dup2(a1.x), dup2(a1.y), dup2(a1.z), dup2(a1.w)};
#pragma unroll
            for (int i = 0; i < 8; i++)
#pragma unroll
                for (int j = 0; j < 4; j++) ffma2(acc[i][j], ad[i], b[j]);
        }
        if (hasNext) {
            int nb = buf ^ 1;
            As[nb][acol + 0][arow] = pa0.x; As[nb][acol + 1][arow] = pa0.y;
            As[nb][acol + 2][arow] = pa0.z; As[nb][acol + 3][arow] = pa0.w;
            As[nb][acol + 0][arow + 64] = pa1.x; As[nb][acol + 1][arow + 64] = pa1.y;
            As[nb][acol + 2][arow + 64] = pa1.z; As[nb][acol + 3][arow + 64] = pa1.w;
            *(float4*)&Bs[nb][brow][bcol]      = pb0;
            *(float4*)&Bs[nb][brow][bcol + 64] = pb1;
            __syncthreads();
            buf = nb;
        }
    }

    // epilogue
    float4 bb0 = *(const float4*)(bias + colBase + tx * 4);
    float4 bb1 = *(const float4*)(bias + colBase + tx * 4 + 64);
    float bc[8] = {bb0.x, bb0.y, bb0.z, bb0.w, bb1.x, bb1.y, bb1.z, bb1.w};

#pragma unroll
    for (int g = 0; g < 2; g++) {
#pragma unroll
        for (int i = 0; i < 4; i++) {
            int ai = g * 4 + i;
            int r = rowBase + g * 64 + ty * 4 + i;
            size_t base0 = (size_t)r * NN + colBase + tx * 4;
#pragma unroll
            for (int half = 0; half < 2; half++) {
                size_t base = base0 + half * 64;
                float2 u0 = unpack2(acc[ai][half * 2 + 0]);
                float2 u1 = unpack2(acc[ai][half * 2 + 1]);
                float vv[4] = {u0.x + bc[half * 4 + 0], u0.y + bc[half * 4 + 1],
                               u1.x + bc[half * 4 + 2], u1.y + bc[half * 4 + 3]};
                if (act == 1) {
#pragma unroll
                    for (int j = 0; j < 4; j++) vv[j] = vv[j] * normcdff(vv[j]);
                }
                if (r1) {
                    float4 q1 = *(const float4*)(r1 + base);
                    vv[0] += q1.x; vv[1] += q1.y; vv[2] += q1.z; vv[3] += q1.w;
                }
                if (r2) {
                    float4 q2 = *(const float4*)(r2 + base);
                    vv[0] += q2.x; vv[1] += q2.y; vv[2] += q2.z; vv[3] += q2.w;
                }
                float4 ov = {vv[0], vv[1], vv[2], vv[3]};
                *(float4*)(C + base) = ov;
            }
        }
    }
}

// ---------------- attention: per (b, h, 32-query tile) ----------------------
static constexpr int QB = 32;
static constexpr int SCS = 516;
static constexpr int KVS = 65;
static constexpr int ATTN_SMEM = (QB * SCS + QB * 64 + 64 * KVS) * 4;

__global__ __launch_bounds__(256) void attn_kernel(
    const float* __restrict__ Q, const float* __restrict__ Kt,
    const float* __restrict__ Vt, const float* __restrict__ bias,
    float* __restrict__ Ctx) {
    extern __shared__ float sm[];
    float* sc = sm;
    float* qs = sm + QB * SCS;
    float* kv = qs + QB * 64;
    const int tid = threadIdx.x;
    const int q0 = blockIdx.x * QB, h = blockIdx.y, b = blockIdx.z;

    for (int i = tid; i < QB * 16; i += 256) {
        int r = i >> 4, c = (i & 15) << 2;
        *(float4*)&qs[r * 64 + c] =
            *(const float4*)&Q[(size_t)(b * S_ + q0 + r) * D_ + h * DH_ + c];
    }
    const int qi = tid >> 3, jr = tid & 7;

    for (int kb = 0; kb < S_; kb += 64) {
        __syncthreads();
        for (int i = tid; i < 64 * 16; i += 256) {
            int r = i >> 4, c = (i & 15) << 2;
            float4 f = *(const float4*)&Kt[(size_t)(b * S_ + kb + r) * D_ + h * DH_ + c];
            kv[r * KVS + c] = f.x; kv[r * KVS + c + 1] = f.y;
            kv[r * KVS + c + 2] = f.z; kv[r * KVS + c + 3] = f.w;
        }
        __syncthreads();
        float acc[8] = {};
#pragma unroll 8
        for (int dd = 0; dd < 64; dd++) {
            float qv = qs[qi * 64 + dd];
#pragma unroll
            for (int t = 0; t < 8; t++) acc[t] += qv * kv[(jr + 8 * t) * KVS + dd];
        }
#pragma unroll
        for (int t = 0; t < 8; t++) {
            int j = jr + 8 * t;
            int rel = (q0 + qi) - (kb + j) + (P_ - 1);
            sc[qi * SCS + kb + j] = acc[t] * 0.125f + __ldg(&bias[rel * H_ + h]);
        }
    }
    __syncthreads();

    {
        int w = tid >> 5, lane = tid & 31;
#pragma unroll
        for (int rr = 0; rr < QB / 8; rr++) {
            int r = w * (QB / 8) + rr;
            float m = -1e30f;
            for (int c = lane; c < S_; c += 32) m = fmaxf(m, sc[r * SCS + c]);
#pragma unroll
            for (int o = 16; o > 0; o >>= 1) m = fmaxf(m, __shfl_xor_sync(0xffffffffu, m, o));
            float sum = 0.f;
            for (int c = lane; c < S_; c += 32) {
                float e = expf(sc[r * SCS + c] - m);
                sc[r * SCS + c] = e;
                sum += e;
            }
#pragma unroll
            for (int o = 16; o > 0; o >>= 1) sum += __shfl_xor_sync(0xffffffffu, sum, o);
            float inv = 1.0f / sum;
            for (int c = lane; c < S_; c += 32) sc[r * SCS + c] *= inv;
        }
    }

    float cacc[8] = {};
    for (int kb = 0; kb < S_; kb += 64) {
        __syncthreads();
        for (int i = tid; i < 64 * 16; i += 256) {
            int r = i >> 4, c = (i & 15) << 2;
            float4 f = *(const float4*)&Vt[(size_t)(b * S_ + kb + r) * D_ + h * DH_ + c];
            kv[r * KVS + c] = f.x; kv[r * KVS + c + 1] = f.y;
            kv[r * KVS + c + 2] = f.z; kv[r * KVS + c + 3] = f.w;
        }
        __syncthreads();
#pragma unroll 8
        for (int j = 0; j < 64; j++) {
            float a = sc[qi * SCS + kb + j];
#pragma unroll
            for (int t = 0; t < 8; t++) cacc[t] += a * kv[j * KVS + jr + 8 * t];
        }
    }
#pragma unroll
    for (int t = 0; t < 8; t++)
        Ctx[(size_t)(b * S_ + q0 + qi) * D_ + h * DH_ + jr + 8 * t] = cacc[t];
}

// ---------------- launch ----------------------------------------------------
extern "C" void kernel_launch(void* const* d_in, const int* in_sizes, int n_in,
                              void* d_out, int out_size) {
    (void)in_sizes; (void)n_in; (void)out_size;
    const float* x    = (const float*)d_in[0];
    const float* pe   = (const float*)d_in[1];
    const float* wq   = (const float*)d_in[2];
    const float* bq   = (const float*)d_in[3];
    const float* wk   = (const float*)d_in[4];
    const float* bk   = (const float*)d_in[5];
    const float* wv   = (const float*)d_in[6];
    const float* bv   = (const float*)d_in[7];
    const float* wo   = (const float*)d_in[8];
    const float* bo   = (const float*)d_in[9];
    const float* bt   = (const float*)d_in[10];
    const float* w1   = (const float*)d_in[11];
    const float* b1   = (const float*)d_in[12];
    const float* w2   = (const float*)d_in[13];
    const float* b2   = (const float*)d_in[14];
    const float* ln1g = (const float*)d_in[15];
    const float* ln1b = (const float*)d_in[16];
    const float* ln2g = (const float*)d_in[17];
    const float* ln2b = (const float*)d_in[18];
    float* out = (float*)d_out;

    float *hb, *xn, *q, *k, *v, *ctx, *o1, *f1;
    cudaGetSymbolAddress((void**)&hb,  g_h);
    cudaGetSymbolAddress((void**)&xn,  g_xn);
    cudaGetSymbolAddress((void**)&q,   g_q);
    cudaGetSymbolAddress((void**)&k,   g_k);
    cudaGetSymbolAddress((void**)&v,   g_v);
    cudaGetSymbolAddress((void**)&ctx, g_ctx);
    cudaGetSymbolAddress((void**)&o1,  g_out1);
    cudaGetSymbolAddress((void**)&f1,  g_ffn1);

    cudaFuncSetAttribute(attn_kernel, cudaFuncAttributeMaxDynamicSharedMemorySize, ATTN_SMEM);

    dim3 gD(D_ / 128, M_ / 128);   // (8, 64)
    dim3 gF(F_ / 128, M_ / 128);   // (32, 64)
    dim3 gAttn(S_ / QB, H_, B_);

    addpe_kernel<<<(M_ * D_) / 256, 256>>>(x, pe, hb);

    for (int l = 0; l < L_; l++) {
        size_t oDD = (size_t)l * D_ * D_;
        size_t oDF = (size_t)l * D_ * F_;
        size_t oD  = (size_t)l * D_;
        size_t oF  = (size_t)l * F_;

        ln_kernel<<<M_, 256>>>(hb, ln1g + oD, ln1b + oD, xn);
        gemm2_kernel<<<gD, 256>>>(xn, wq + oDD, bq + oD, nullptr, nullptr, q, D_, D_, 0);
        gemm2_kernel<<<gD, 256>>>(xn, wk + oDD, bk + oD, nullptr, nullptr, k, D_, D_, 0);
        gemm2_kernel<<<gD, 256>>>(xn, wv + oDD, bv + oD, nullptr, nullptr, v, D_, D_, 0);

        attn_kernel<<<gAttn, 256, ATTN_SMEM>>>(q, k, v, bt + (size_t)l * (2 * P_ - 1) * H_, ctx);

        gemm2_kernel<<<gD, 256>>>(ctx, wo + oDD, bo + oD, hb, nullptr, o1, D_, D_, 0);

        ln_kernel<<<M_, 256>>>(o1, ln2g + oD, ln2b + oD, xn);
        gemm2_kernel<<<gF, 256>>>(xn, w1 + oDF, b1 + oF, nullptr, nullptr, f1, F_, D_, 1);
        float* dst = (l == L_ - 1) ? out : hb;
        gemm2_kernel<<<gD, 256>>>(f1, w2 + oDF, b2 + oD, o1, hb, dst, D_, F_, 0);
    }
}

// round 4
// speedup vs baseline: 2.3472x; 1.6389x over previous
#include <cuda_runtime.h>
#include <cuda_bf16.h>
#include <math.h>
#include <cstdint>

static constexpr int L_ = 6, D_ = 1024, H_ = 16, F_ = 4096, S_ = 512, B_ = 16, P_ = 512;
static constexpr int DH_ = D_ / H_;          // 64
static constexpr int M_ = B_ * S_;           // 8192

// ---------------- scratch (device globals; no allocations allowed) ----------
__device__ __align__(16) float g_h[(size_t)M_ * D_];
__device__ __align__(16) float g_q[(size_t)M_ * D_];
__device__ __align__(16) float g_k[(size_t)M_ * D_];
__device__ __align__(16) float g_v[(size_t)M_ * D_];
__device__ __align__(16) float g_ctx[(size_t)M_ * D_];
__device__ __align__(16) float g_out1[(size_t)M_ * D_];

// activation hi/lo (bf16 split)
__device__ __align__(16) __nv_bfloat16 g_xn_h[(size_t)M_ * D_];
__device__ __align__(16) __nv_bfloat16 g_xn_l[(size_t)M_ * D_];
__device__ __align__(16) __nv_bfloat16 g_ctx_h[(size_t)M_ * D_];
__device__ __align__(16) __nv_bfloat16 g_ctx_l[(size_t)M_ * D_];
__device__ __align__(16) __nv_bfloat16 g_f1_h[(size_t)M_ * F_];
__device__ __align__(16) __nv_bfloat16 g_f1_l[(size_t)M_ * F_];

// transposed+split weights: [N,K] bf16
__device__ __align__(16) __nv_bfloat16 g_wqT_h[(size_t)L_ * D_ * D_];
__device__ __align__(16) __nv_bfloat16 g_wqT_l[(size_t)L_ * D_ * D_];
__device__ __align__(16) __nv_bfloat16 g_wkT_h[(size_t)L_ * D_ * D_];
__device__ __align__(16) __nv_bfloat16 g_wkT_l[(size_t)L_ * D_ * D_];
__device__ __align__(16) __nv_bfloat16 g_wvT_h[(size_t)L_ * D_ * D_];
__device__ __align__(16) __nv_bfloat16 g_wvT_l[(size_t)L_ * D_ * D_];
__device__ __align__(16) __nv_bfloat16 g_woT_h[(size_t)L_ * D_ * D_];
__device__ __align__(16) __nv_bfloat16 g_woT_l[(size_t)L_ * D_ * D_];
__device__ __align__(16) __nv_bfloat16 g_w1T_h[(size_t)L_ * D_ * F_];
__device__ __align__(16) __nv_bfloat16 g_w1T_l[(size_t)L_ * D_ * F_];
__device__ __align__(16) __nv_bfloat16 g_w2T_h[(size_t)L_ * F_ * D_];
__device__ __align__(16) __nv_bfloat16 g_w2T_l[(size_t)L_ * F_ * D_];

// ---------------- PTX helpers (sm_80-era, legal on plain sm_103) -------------
__device__ __forceinline__ uint32_t smem_u32(const void* p) {
    uint32_t a;
    asm("{ .reg .u64 t; cvta.to.shared.u64 t, %1; cvt.u32.u64 %0, t; }" : "=r"(a) : "l"(p));
    return a;
}
__device__ __forceinline__ void ldsm4(uint32_t* r, uint32_t addr) {
    asm volatile("ldmatrix.sync.aligned.m8n8.x4.shared.b16 {%0,%1,%2,%3}, [%4];"
                 : "=r"(r[0]), "=r"(r[1]), "=r"(r[2]), "=r"(r[3]) : "r"(addr));
}
__device__ __forceinline__ void mma16816(float* d, const uint32_t* a, uint32_t b0, uint32_t b1) {
    asm volatile("mma.sync.aligned.m16n8k16.row.col.f32.bf16.bf16.f32 "
                 "{%0,%1,%2,%3}, {%4,%5,%6,%7}, {%8,%9}, {%0,%1,%2,%3};"
                 : "+f"(d[0]), "+f"(d[1]), "+f"(d[2]), "+f"(d[3])
                 : "r"(a[0]), "r"(a[1]), "r"(a[2]), "r"(a[3]), "r"(b0), "r"(b1));
}
#define CPA(dst, src)  asm volatile("cp.async.cg.shared.global [%0], [%1], 16;" :: "r"(dst), "l"(src))
#define CPA_COMMIT()   asm volatile("cp.async.commit_group;" ::: "memory")
#define CPA_WAIT1()    asm volatile("cp.async.wait_group 1;" ::: "memory")
#define CPA_WAIT0()    asm volatile("cp.async.wait_group 0;" ::: "memory")

__device__ __forceinline__ uint32_t swz(uint32_t off) { return off ^ ((off >> 3) & 0x70); }
// row_byte multiple of 128, col_byte < 128: swizzle applies XOR of row bits into col
__device__ __forceinline__ uint32_t smx(uint32_t row_byte, uint32_t col_byte) {
    return row_byte + (col_byte ^ ((row_byte >> 3) & 0x70));
}

// ---------------- h = x + pe -------------------------------------------------
__global__ __launch_bounds__(256) void addpe_kernel(const float* __restrict__ x,
                                                    const float* __restrict__ pe,
                                                    float* __restrict__ h) {
    int i = blockIdx.x * 256 + threadIdx.x;
    h[i] = x[i] + pe[i & (S_ * D_ - 1)];
}

// ---------------- weight transpose + bf16 split: W[K,N] -> T[N,K] hi/lo -----
__global__ __launch_bounds__(256) void wtrans_kernel(const float* __restrict__ W,
                                                     __nv_bfloat16* __restrict__ Th,
                                                     __nv_bfloat16* __restrict__ Tl,
                                                     int K, int N) {
    __shared__ float t[32][33];
    size_t off = (size_t)blockIdx.z * K * N;
    int k0 = blockIdx.y * 32, n0 = blockIdx.x * 32;
    int tx = threadIdx.x & 31, ty = threadIdx.x >> 5;   // 32 x 8
#pragma unroll
    for (int i = 0; i < 32; i += 8)
        t[ty + i][tx] = W[off + (size_t)(k0 + ty + i) * N + n0 + tx];
    __syncthreads();
#pragma unroll
    for (int i = 0; i < 32; i += 8) {
        float v = t[tx][ty + i];
        __nv_bfloat16 hi = __float2bfloat16(v);
        size_t idx = off + (size_t)(n0 + ty + i) * K + k0 + tx;
        Th[idx] = hi;
        Tl[idx] = __float2bfloat16(v - __bfloat162float(hi));
    }
}

// ---------------- LayerNorm: fp32 in -> bf16 hi/lo out -----------------------
__global__ __launch_bounds__(256) void ln_kernel(const float* __restrict__ x,
                                                 const float* __restrict__ g,
                                                 const float* __restrict__ b,
                                                 __nv_bfloat16* __restrict__ yh,
                                                 __nv_bfloat16* __restrict__ yl) {
    int row = blockIdx.x, tid = threadIdx.x;
    const float* xr = x + (size_t)row * D_;
    float4 f = *(const float4*)(xr + tid * 4);
    float s  = f.x + f.y + f.z + f.w;
    float ss = f.x * f.x + f.y * f.y + f.z * f.z + f.w * f.w;
#pragma unroll
    for (int o = 16; o > 0; o >>= 1) {
        s  += __shfl_xor_sync(0xffffffffu, s, o);
        ss += __shfl_xor_sync(0xffffffffu, ss, o);
    }
    __shared__ float rs[8], rss[8];
    if ((tid & 31) == 0) { rs[tid >> 5] = s; rss[tid >> 5] = ss; }
    __syncthreads();
    float ts = 0.f, tss = 0.f;
#pragma unroll
    for (int i = 0; i < 8; i++) { ts += rs[i]; tss += rss[i]; }
    float mean = ts * (1.0f / D_);
    float var  = tss * (1.0f / D_) - mean * mean;
    float r    = rsqrtf(var + 1e-6f);
    float4 g4 = *(const float4*)(g + tid * 4);
    float4 b4 = *(const float4*)(b + tid * 4);
    float o[4];
    o[0] = (f.x - mean) * r * g4.x + b4.x;
    o[1] = (f.y - mean) * r * g4.y + b4.y;
    o[2] = (f.z - mean) * r * g4.z + b4.z;
    o[3] = (f.w - mean) * r * g4.w + b4.w;
    size_t base = (size_t)row * D_ + tid * 4;
#pragma unroll
    for (int j = 0; j < 4; j += 2) {
        __nv_bfloat16 h0 = __float2bfloat16(o[j]);
        __nv_bfloat16 h1 = __float2bfloat16(o[j + 1]);
        *(__nv_bfloat162*)(yh + base + j) = __nv_bfloat162(h0, h1);
        *(__nv_bfloat162*)(yl + base + j) = __nv_bfloat162(
            __float2bfloat16(o[j] - __bfloat162float(h0)),
            __float2bfloat16(o[j + 1] - __bfloat162float(h1)));
    }
}

// ---------------- split-bf16 mma.sync GEMM 128x128, Kc=64, cp.async x2 ------
// C = act(A@B^T + bias) + r1 + r2 ; A = Ah+Al [M,KK], B = Bh+Bl [N,KK]
static constexpr int TILEB = 128 * 64 * 2;     // 16 KB per matrix tile
static constexpr int S_AH = 0, S_AL = TILEB, S_BH = 2 * TILEB, S_BL = 3 * TILEB;
static constexpr int STAGEB = 4 * TILEB;       // 64 KB per stage
static constexpr int GEMM_SMEM = 2 * STAGEB;   // 128 KB

__device__ __forceinline__ void tile_cpa(const __nv_bfloat16* __restrict__ g,
                                         int row0, int stride, int k0,
                                         uint32_t sdst, int tid) {
#pragma unroll
    for (int i = 0; i < 4; i++) {
        int idx = i * 256 + tid;          // 0..1023
        int r = idx >> 3, c = idx & 7;
        const __nv_bfloat16* src = g + (size_t)(row0 + r) * stride + k0 + c * 8;
        CPA(sdst + swz(r * 128 + c * 16), src);
    }
}

__global__ __launch_bounds__(256, 1) void gemm_mma_kernel(
    const __nv_bfloat16* __restrict__ Ah, const __nv_bfloat16* __restrict__ Al,
    const __nv_bfloat16* __restrict__ Bh, const __nv_bfloat16* __restrict__ Bl,
    const float* __restrict__ bias, const float* __restrict__ r1,
    const float* __restrict__ r2, float* __restrict__ C,
    __nv_bfloat16* __restrict__ Ch, __nv_bfloat16* __restrict__ Cl,
    int NN, int KK, int act) {
    extern __shared__ char smem[];
    const uint32_t sb = smem_u32(smem);
    const int tid = threadIdx.x;
    const int wid = tid >> 5, lane = tid & 31;
    const int wm = wid >> 2, wn = wid & 3;        // warps 2 x 4; warp tile 64x32
    const int rowBase = blockIdx.y * 128, colBase = blockIdx.x * 128;

    float acc[4][4][4];
#pragma unroll
    for (int i = 0; i < 4; i++)
#pragma unroll
        for (int j = 0; j < 4; j++)
#pragma unroll
            for (int q = 0; q < 4; q++) acc[i][j][q] = 0.f;

    // ldmatrix lane addressing (byte offsets inside a 128x64-bf16 swizzled tile)
    // A frag (m16k16): row = mbase + (lane&15), 16B col = (lane>>4)
    const uint32_t a_row = (uint32_t)((wm * 64 + (lane & 15)) * 128);
    const uint32_t a_col = (uint32_t)((lane >> 4) * 16);
    // B frag pair (n16k16): row = nbase + (lane&7) + ((lane>>4)<<3), col = (lane>>3)&1
    const uint32_t b_row0 = (uint32_t)((wn * 32 + (lane & 7) + ((lane >> 4) << 3)) * 128);
    const uint32_t b_col = (uint32_t)(((lane >> 3) & 1) * 16);

    const int nc = KK / 64;
    // prologue: stage 0
    tile_cpa(Ah, rowBase, KK, 0, sb + S_AH, tid);
    tile_cpa(Al, rowBase, KK, 0, sb + S_AL, tid);
    tile_cpa(Bh, colBase, KK, 0, sb + S_BH, tid);
    tile_cpa(Bl, colBase, KK, 0, sb + S_BL, tid);
    CPA_COMMIT();

    for (int c = 0; c < nc; c++) {
        if (c + 1 < nc) {
            uint32_t st = sb + ((c + 1) & 1) * STAGEB;
            int k0 = (c + 1) * 64;
            tile_cpa(Ah, rowBase, KK, k0, st + S_AH, tid);
            tile_cpa(Al, rowBase, KK, k0, st + S_AL, tid);
            tile_cpa(Bh, colBase, KK, k0, st + S_BH, tid);
            tile_cpa(Bl, colBase, KK, k0, st + S_BL, tid);
            CPA_COMMIT();
            CPA_WAIT1();
        } else {
            CPA_WAIT0();
        }
        __syncthreads();
        uint32_t st = sb + (c & 1) * STAGEB;

#pragma unroll
        for (int ks = 0; ks < 4; ks++) {
            const uint32_t kb = ks * 32;
            uint32_t bh[2][4], bl[2][4];
#pragma unroll
            for (int g = 0; g < 2; g++) {
                uint32_t roff = b_row0 + (uint32_t)(g * 16 * 128);
                ldsm4(bh[g], st + S_BH + smx(roff, kb + b_col));
                ldsm4(bl[g], st + S_BL + smx(roff, kb + b_col));
            }
#pragma unroll
            for (int mi = 0; mi < 4; mi++) {
                uint32_t roff = a_row + (uint32_t)(mi * 16 * 128);
                uint32_t a_h[4], a_l[4];
                ldsm4(a_h, st + S_AH + smx(roff, kb + a_col));
                ldsm4(a_l, st + S_AL + smx(roff, kb + a_col));
#pragma unroll
                for (int nj = 0; nj < 4; nj++) {
                    int g = nj >> 1, o = (nj & 1) * 2;   // regs {o, o+1}? (see map below)
                    // ldmatrix x4 B map: r0,r1 = n(0..7) frag (k lo, k hi); r2,r3 = n(8..15)
                    uint32_t h0 = bh[g][o], h1 = bh[g][o + 1];
                    uint32_t l0 = bl[g][o], l1 = bl[g][o + 1];
                    mma16816(acc[mi][nj], a_h, h0, h1);
                    mma16816(acc[mi][nj], a_h, l0, l1);
                    mma16816(acc[mi][nj], a_l, h0, h1);
                }
            }
        }
        __syncthreads();
    }

    // epilogue: acc frag (m16n8): thread holds (tq, tr*2..+1) and (tq+8, ...)
    const int tq = lane >> 2, tr = lane & 3;
#pragma unroll
    for (int mi = 0; mi < 4; mi++) {
#pragma unroll
        for (int nj = 0; nj < 4; nj++) {
            int n = colBase + wn * 32 + nj * 8 + tr * 2;
            float2 bb = *(const float2*)(bias + n);
#pragma unroll
            for (int half = 0; half < 2; half++) {
                int m = rowBase + wm * 64 + mi * 16 + tq + half * 8;
                size_t base = (size_t)m * NN + n;
                float v0 = acc[mi][nj][half * 2 + 0] + bb.x;
                float v1 = acc[mi][nj][half * 2 + 1] + bb.y;
                if (act == 1) { v0 = v0 * normcdff(v0); v1 = v1 * normcdff(v1); }
                if (r1) { float2 q = *(const float2*)(r1 + base); v0 += q.x; v1 += q.y; }
                if (r2) { float2 q = *(const float2*)(r2 + base); v0 += q.x; v1 += q.y; }
                if (C) { float2 ov = {v0, v1}; *(float2*)(C + base) = ov; }
                if (Ch) {
                    __nv_bfloat16 h0 = __float2bfloat16(v0);
                    __nv_bfloat16 h1 = __float2bfloat16(v1);
                    *(__nv_bfloat162*)(Ch + base) = __nv_bfloat162(h0, h1);
                    *(__nv_bfloat162*)(Cl + base) = __nv_bfloat162(
                        __float2bfloat16(v0 - __bfloat162float(h0)),
                        __float2bfloat16(v1 - __bfloat162float(h1)));
                }
            }
        }
    }
}

// ---------------- attention: per (b, h, 32-query tile) ----------------------
static constexpr int QB = 32;
static constexpr int SCS = 516;
static constexpr int KVS = 65;
static constexpr int ATTN_SMEM = (QB * SCS + QB * 64 + 64 * KVS) * 4;

__global__ __launch_bounds__(256) void attn_kernel(
    const float* __restrict__ Q, const float* __restrict__ Kt,
    const float* __restrict__ Vt, const float* __restrict__ bias,
    float* __restrict__ Ctx, __nv_bfloat16* __restrict__ Ctxh,
    __nv_bfloat16* __restrict__ Ctxl) {
    extern __shared__ float sm[];
    float* sc = sm;
    float* qs = sm + QB * SCS;
    float* kv = qs + QB * 64;
    const int tid = threadIdx.x;
    const int q0 = blockIdx.x * QB, h = blockIdx.y, b = blockIdx.z;

    for (int i = tid; i < QB * 16; i += 256) {
        int r = i >> 4, c = (i & 15) << 2;
        *(float4*)&qs[r * 64 + c] =
            *(const float4*)&Q[(size_t)(b * S_ + q0 + r) * D_ + h * DH_ + c];
    }
    const int qi = tid >> 3, jr = tid & 7;

    for (int kb = 0; kb < S_; kb += 64) {
        __syncthreads();
        for (int i = tid; i < 64 * 16; i += 256) {
            int r = i >> 4, c = (i & 15) << 2;
            float4 f = *(const float4*)&Kt[(size_t)(b * S_ + kb + r) * D_ + h * DH_ + c];
            kv[r * KVS + c] = f.x; kv[r * KVS + c + 1] = f.y;
            kv[r * KVS + c + 2] = f.z; kv[r * KVS + c + 3] = f.w;
        }
        __syncthreads();
        float acc[8] = {};
#pragma unroll 8
        for (int dd = 0; dd < 64; dd++) {
            float qv = qs[qi * 64 + dd];
#pragma unroll
            for (int t = 0; t < 8; t++) acc[t] += qv * kv[(jr + 8 * t) * KVS + dd];
        }
#pragma unroll
        for (int t = 0; t < 8; t++) {
            int j = jr + 8 * t;
            int rel = (q0 + qi) - (kb + j) + (P_ - 1);
            sc[qi * SCS + kb + j] = acc[t] * 0.125f + __ldg(&bias[rel * H_ + h]);
        }
    }
    __syncthreads();

    {
        int w = tid >> 5, lane = tid & 31;
#pragma unroll
        for (int rr = 0; rr < QB / 8; rr++) {
            int r = w * (QB / 8) + rr;
            float m = -1e30f;
            for (int c = lane; c < S_; c += 32) m = fmaxf(m, sc[r * SCS + c]);
#pragma unroll
            for (int o = 16; o > 0; o >>= 1) m = fmaxf(m, __shfl_xor_sync(0xffffffffu, m, o));
            float sum = 0.f;
            for (int c = lane; c < S_; c += 32) {
                float e = expf(sc[r * SCS + c] - m);
                sc[r * SCS + c] = e;
                sum += e;
            }
#pragma unroll
            for (int o = 16; o > 0; o >>= 1) sum += __shfl_xor_sync(0xffffffffu, sum, o);
            float inv = 1.0f / sum;
            for (int c = lane; c < S_; c += 32) sc[r * SCS + c] *= inv;
        }
    }

    float cacc[8] = {};
    for (int kb = 0; kb < S_; kb += 64) {
        __syncthreads();
        for (int i = tid; i < 64 * 16; i += 256) {
            int r = i >> 4, c = (i & 15) << 2;
            float4 f = *(const float4*)&Vt[(size_t)(b * S_ + kb + r) * D_ + h * DH_ + c];
            kv[r * KVS + c] = f.x; kv[r * KVS + c + 1] = f.y;
            kv[r * KVS + c + 2] = f.z; kv[r * KVS + c + 3] = f.w;
        }
        __syncthreads();
#pragma unroll 8
        for (int j = 0; j < 64; j++) {
            float a = sc[qi * SCS + kb + j];
#pragma unroll
            for (int t = 0; t < 8; t++) cacc[t] += a * kv[j * KVS + jr + 8 * t];
        }
    }
#pragma unroll
    for (int t = 0; t < 8; t++) {
        size_t idx = (size_t)(b * S_ + q0 + qi) * D_ + h * DH_ + jr + 8 * t;
        float cv = cacc[t];
        Ctx[idx] = cv;
        __nv_bfloat16 hh = __float2bfloat16(cv);
        Ctxh[idx] = hh;
        Ctxl[idx] = __float2bfloat16(cv - __bfloat162float(hh));
    }
}

// ---------------- launch ----------------------------------------------------
extern "C" void kernel_launch(void* const* d_in, const int* in_sizes, int n_in,
                              void* d_out, int out_size) {
    (void)in_sizes; (void)n_in; (void)out_size;
    const float* x    = (const float*)d_in[0];
    const float* pe   = (const float*)d_in[1];
    const float* wq   = (const float*)d_in[2];
    const float* bq   = (const float*)d_in[3];
    const float* wk   = (const float*)d_in[4];
    const float* bk   = (const float*)d_in[5];
    const float* wv   = (const float*)d_in[6];
    const float* bv   = (const float*)d_in[7];
    const float* wo   = (const float*)d_in[8];
    const float* bo   = (const float*)d_in[9];
    const float* bt   = (const float*)d_in[10];
    const float* w1   = (const float*)d_in[11];
    const float* b1   = (const float*)d_in[12];
    const float* w2   = (const float*)d_in[13];
    const float* b2   = (const float*)d_in[14];
    const float* ln1g = (const float*)d_in[15];
    const float* ln1b = (const float*)d_in[16];
    const float* ln2g = (const float*)d_in[17];
    const float* ln2b = (const float*)d_in[18];
    float* out = (float*)d_out;

    float *hb, *q, *k, *v, *ctx, *o1;
    __nv_bfloat16 *xnh, *xnl, *cxh, *cxl, *f1h, *f1l;
    __nv_bfloat16 *wqh, *wql, *wkh, *wkl, *wvh, *wvl, *woh, *wol, *w1h, *w1l, *w2h, *w2l;
    cudaGetSymbolAddress((void**)&hb,  g_h);
    cudaGetSymbolAddress((void**)&q,   g_q);
    cudaGetSymbolAddress((void**)&k,   g_k);
    cudaGetSymbolAddress((void**)&v,   g_v);
    cudaGetSymbolAddress((void**)&ctx, g_ctx);
    cudaGetSymbolAddress((void**)&o1,  g_out1);
    cudaGetSymbolAddress((void**)&xnh, g_xn_h);  cudaGetSymbolAddress((void**)&xnl, g_xn_l);
    cudaGetSymbolAddress((void**)&cxh, g_ctx_h); cudaGetSymbolAddress((void**)&cxl, g_ctx_l);
    cudaGetSymbolAddress((void**)&f1h, g_f1_h);  cudaGetSymbolAddress((void**)&f1l, g_f1_l);
    cudaGetSymbolAddress((void**)&wqh, g_wqT_h); cudaGetSymbolAddress((void**)&wql, g_wqT_l);
    cudaGetSymbolAddress((void**)&wkh, g_wkT_h); cudaGetSymbolAddress((void**)&wkl, g_wkT_l);
    cudaGetSymbolAddress((void**)&wvh, g_wvT_h); cudaGetSymbolAddress((void**)&wvl, g_wvT_l);
    cudaGetSymbolAddress((void**)&woh, g_woT_h); cudaGetSymbolAddress((void**)&wol, g_woT_l);
    cudaGetSymbolAddress((void**)&w1h, g_w1T_h); cudaGetSymbolAddress((void**)&w1l, g_w1T_l);
    cudaGetSymbolAddress((void**)&w2h, g_w2T_h); cudaGetSymbolAddress((void**)&w2l, g_w2T_l);

    cudaFuncSetAttribute(attn_kernel,     cudaFuncAttributeMaxDynamicSharedMemorySize, ATTN_SMEM);
    cudaFuncSetAttribute(gemm_mma_kernel, cudaFuncAttributeMaxDynamicSharedMemorySize, GEMM_SMEM);

    // prologue: h = x + pe ; weight transpose + split
    addpe_kernel<<<(M_ * D_) / 256, 256>>>(x, pe, hb);
    {
        dim3 gdd(D_ / 32, D_ / 32, L_);
        wtrans_kernel<<<gdd, 256>>>(wq, wqh, wql, D_, D_);
        wtrans_kernel<<<gdd, 256>>>(wk, wkh, wkl, D_, D_);
        wtrans_kernel<<<gdd, 256>>>(wv, wvh, wvl, D_, D_);
        wtrans_kernel<<<gdd, 256>>>(wo, woh, wol, D_, D_);
        dim3 g1(F_ / 32, D_ / 32, L_);
        wtrans_kernel<<<g1, 256>>>(w1, w1h, w1l, D_, F_);
        dim3 g2(D_ / 32, F_ / 32, L_);
        wtrans_kernel<<<g2, 256>>>(w2, w2h, w2l, F_, D_);
    }

    dim3 gD(D_ / 128, M_ / 128);   // (8, 64)
    dim3 gF(F_ / 128, M_ / 128);   // (32, 64)
    dim3 gAttn(S_ / QB, H_, B_);

    for (int l = 0; l < L_; l++) {
        size_t oDD = (size_t)l * D_ * D_;
        size_t oDF = (size_t)l * D_ * F_;
        size_t oD  = (size_t)l * D_;
        size_t oF  = (size_t)l * F_;

        ln_kernel<<<M_, 256>>>(hb, ln1g + oD, ln1b + oD, xnh, xnl);
        gemm_mma_kernel<<<gD, 256, GEMM_SMEM>>>(xnh, xnl, wqh + oDD, wql + oDD,
            bq + oD, nullptr, nullptr, q, nullptr, nullptr, D_, D_, 0);
        gemm_mma_kernel<<<gD, 256, GEMM_SMEM>>>(xnh, xnl, wkh + oDD, wkl + oDD,
            bk + oD, nullptr, nullptr, k, nullptr, nullptr, D_, D_, 0);
        gemm_mma_kernel<<<gD, 256, GEMM_SMEM>>>(xnh, xnl, wvh + oDD, wvl + oDD,
            bv + oD, nullptr, nullptr, v, nullptr, nullptr, D_, D_, 0);

        attn_kernel<<<gAttn, 256, ATTN_SMEM>>>(q, k, v,
            bt + (size_t)l * (2 * P_ - 1) * H_, ctx, cxh, cxl);

        // out1 = ctx @ wo + bo + h
        gemm_mma_kernel<<<gD, 256, GEMM_SMEM>>>(cxh, cxl, woh + oDD, wol + oDD,
            bo + oD, hb, nullptr, o1, nullptr, nullptr, D_, D_, 0);

        ln_kernel<<<M_, 256>>>(o1, ln2g + oD, ln2b + oD, xnh, xnl);
        // f1 = gelu(xn2 @ w1 + b1)  (bf16 hi/lo only)
        gemm_mma_kernel<<<gF, 256, GEMM_SMEM>>>(xnh, xnl, w1h + oDF, w1l + oDF,
            b1 + oF, nullptr, nullptr, nullptr, f1h, f1l, F_, D_, 1);
        // h_new = f1 @ w2 + b2 + out1 + h_old
        float* dst = (l == L_ - 1) ? out : hb;
        gemm_mma_kernel<<<gD, 256, GEMM_SMEM>>>(f1h, f1l, w2h + oDF, w2l + oDF,
            b2 + oD, o1, hb, dst, nullptr, nullptr, D_, F_, 0);
    }
}

// round 5
// speedup vs baseline: 3.4067x; 1.4514x over previous
#include <cuda_runtime.h>
#include <cuda_bf16.h>
#include <math.h>
#include <cstdint>

using bf16 = __nv_bfloat16;

static constexpr int L_ = 6, D_ = 1024, H_ = 16, F_ = 4096, S_ = 512, B_ = 16, P_ = 512;
static constexpr int DH_ = D_ / H_;          // 64
static constexpr int M_ = B_ * S_;           // 8192

// ---------------- scratch (device globals; no allocations allowed) ----------
__device__ __align__(16) float g_h[(size_t)M_ * D_];
__device__ __align__(16) float g_out1[(size_t)M_ * D_];

__device__ __align__(16) bf16 g_xn_h[(size_t)M_ * D_];
__device__ __align__(16) bf16 g_xn_l[(size_t)M_ * D_];
__device__ __align__(16) bf16 g_q_h[(size_t)M_ * D_];
__device__ __align__(16) bf16 g_q_l[(size_t)M_ * D_];
__device__ __align__(16) bf16 g_k_h[(size_t)M_ * D_];
__device__ __align__(16) bf16 g_k_l[(size_t)M_ * D_];
__device__ __align__(16) bf16 g_v_h[(size_t)M_ * D_];
__device__ __align__(16) bf16 g_v_l[(size_t)M_ * D_];
__device__ __align__(16) bf16 g_ctx_h[(size_t)M_ * D_];
__device__ __align__(16) bf16 g_ctx_l[(size_t)M_ * D_];
__device__ __align__(16) bf16 g_f1_h[(size_t)M_ * F_];
__device__ __align__(16) bf16 g_f1_l[(size_t)M_ * F_];

// transposed+split weights: [N,K] bf16
__device__ __align__(16) bf16 g_wqT_h[(size_t)L_ * D_ * D_];
__device__ __align__(16) bf16 g_wqT_l[(size_t)L_ * D_ * D_];
__device__ __align__(16) bf16 g_wkT_h[(size_t)L_ * D_ * D_];
__device__ __align__(16) bf16 g_wkT_l[(size_t)L_ * D_ * D_];
__device__ __align__(16) bf16 g_wvT_h[(size_t)L_ * D_ * D_];
__device__ __align__(16) bf16 g_wvT_l[(size_t)L_ * D_ * D_];
__device__ __align__(16) bf16 g_woT_h[(size_t)L_ * D_ * D_];
__device__ __align__(16) bf16 g_woT_l[(size_t)L_ * D_ * D_];
__device__ __align__(16) bf16 g_w1T_h[(size_t)L_ * D_ * F_];
__device__ __align__(16) bf16 g_w1T_l[(size_t)L_ * D_ * F_];
__device__ __align__(16) bf16 g_w2T_h[(size_t)L_ * F_ * D_];
__device__ __align__(16) bf16 g_w2T_l[(size_t)L_ * F_ * D_];

// ---------------- PTX helpers (sm_80-era, legal on plain sm_103) -------------
__device__ __forceinline__ uint32_t smem_u32(const void* p) {
    uint32_t a;
    asm("{ .reg .u64 t; cvta.to.shared.u64 t, %1; cvt.u32.u64 %0, t; }" : "=r"(a) : "l"(p));
    return a;
}
__device__ __forceinline__ void ldsm4(uint32_t* r, uint32_t addr) {
    asm volatile("ldmatrix.sync.aligned.m8n8.x4.shared.b16 {%0,%1,%2,%3}, [%4];"
                 : "=r"(r[0]), "=r"(r[1]), "=r"(r[2]), "=r"(r[3]) : "r"(addr));
}
__device__ __forceinline__ void ldsm4t(uint32_t* r, uint32_t addr) {
    asm volatile("ldmatrix.sync.aligned.m8n8.x4.trans.shared.b16 {%0,%1,%2,%3}, [%4];"
                 : "=r"(r[0]), "=r"(r[1]), "=r"(r[2]), "=r"(r[3]) : "r"(addr));
}
__device__ __forceinline__ void mma16816(float* d, const uint32_t* a, uint32_t b0, uint32_t b1) {
    asm volatile("mma.sync.aligned.m16n8k16.row.col.f32.bf16.bf16.f32 "
                 "{%0,%1,%2,%3}, {%4,%5,%6,%7}, {%8,%9}, {%0,%1,%2,%3};"
                 : "+f"(d[0]), "+f"(d[1]), "+f"(d[2]), "+f"(d[3])
                 : "r"(a[0]), "r"(a[1]), "r"(a[2]), "r"(a[3]), "r"(b0), "r"(b1));
}
#define CPA(dst, src)  asm volatile("cp.async.cg.shared.global [%0], [%1], 16;" :: "r"(dst), "l"(src))
#define CPA_COMMIT()   asm volatile("cp.async.commit_group;" ::: "memory")
#define CPA_WAIT1()    asm volatile("cp.async.wait_group 1;" ::: "memory")
#define CPA_WAIT0()    asm volatile("cp.async.wait_group 0;" ::: "memory")

__device__ __forceinline__ uint32_t swz(uint32_t off) { return off ^ ((off >> 3) & 0x70); }
__device__ __forceinline__ uint32_t smx(uint32_t row_byte, uint32_t col_byte) {
    return row_byte + (col_byte ^ ((row_byte >> 3) & 0x70));
}

// ---------------- h = x + pe -------------------------------------------------
__global__ __launch_bounds__(256) void addpe_kernel(const float* __restrict__ x,
                                                    const float* __restrict__ pe,
                                                    float* __restrict__ h) {
    int i = blockIdx.x * 256 + threadIdx.x;
    h[i] = x[i] + pe[i & (S_ * D_ - 1)];
}

// ---------------- weight transpose + bf16 split: W[K,N] -> T[N,K] hi/lo -----
__global__ __launch_bounds__(256) void wtrans_kernel(const float* __restrict__ W,
                                                     bf16* __restrict__ Th,
                                                     bf16* __restrict__ Tl,
                                                     int K, int N) {
    __shared__ float t[32][33];
    size_t off = (size_t)blockIdx.z * K * N;
    int k0 = blockIdx.y * 32, n0 = blockIdx.x * 32;
    int tx = threadIdx.x & 31, ty = threadIdx.x >> 5;
#pragma unroll
    for (int i = 0; i < 32; i += 8)
        t[ty + i][tx] = W[off + (size_t)(k0 + ty + i) * N + n0 + tx];
    __syncthreads();
#pragma unroll
    for (int i = 0; i < 32; i += 8) {
        float v = t[tx][ty + i];
        bf16 hi = __float2bfloat16(v);
        size_t idx = off + (size_t)(n0 + ty + i) * K + k0 + tx;
        Th[idx] = hi;
        Tl[idx] = __float2bfloat16(v - __bfloat162float(hi));
    }
}

// ---------------- LayerNorm: fp32 in -> bf16 hi/lo out -----------------------
__global__ __launch_bounds__(256) void ln_kernel(const float* __restrict__ x,
                                                 const float* __restrict__ g,
                                                 const float* __restrict__ b,
                                                 bf16* __restrict__ yh,
                                                 bf16* __restrict__ yl) {
    int row = blockIdx.x, tid = threadIdx.x;
    const float* xr = x + (size_t)row * D_;
    float4 f = *(const float4*)(xr + tid * 4);
    float s  = f.x + f.y + f.z + f.w;
    float ss = f.x * f.x + f.y * f.y + f.z * f.z + f.w * f.w;
#pragma unroll
    for (int o = 16; o > 0; o >>= 1) {
        s  += __shfl_xor_sync(0xffffffffu, s, o);
        ss += __shfl_xor_sync(0xffffffffu, ss, o);
    }
    __shared__ float rs[8], rss[8];
    if ((tid & 31) == 0) { rs[tid >> 5] = s; rss[tid >> 5] = ss; }
    __syncthreads();
    float ts = 0.f, tss = 0.f;
#pragma unroll
    for (int i = 0; i < 8; i++) { ts += rs[i]; tss += rss[i]; }
    float mean = ts * (1.0f / D_);
    float var  = tss * (1.0f / D_) - mean * mean;
    float r    = rsqrtf(var + 1e-6f);
    float4 g4 = *(const float4*)(g + tid * 4);
    float4 b4 = *(const float4*)(b + tid * 4);
    float o[4];
    o[0] = (f.x - mean) * r * g4.x + b4.x;
    o[1] = (f.y - mean) * r * g4.y + b4.y;
    o[2] = (f.z - mean) * r * g4.z + b4.z;
    o[3] = (f.w - mean) * r * g4.w + b4.w;
    size_t base = (size_t)row * D_ + tid * 4;
#pragma unroll
    for (int j = 0; j < 4; j += 2) {
        bf16 h0 = __float2bfloat16(o[j]);
        bf16 h1 = __float2bfloat16(o[j + 1]);
        *(__nv_bfloat162*)(yh + base + j) = __nv_bfloat162(h0, h1);
        *(__nv_bfloat162*)(yl + base + j) = __nv_bfloat162(
            __float2bfloat16(o[j] - __bfloat162float(h0)),
            __float2bfloat16(o[j + 1] - __bfloat162float(h1)));
    }
}

// ---------------- split-bf16 mma.sync GEMM 128x128, Kc=64, cp.async x2 ------
static constexpr int TILEB = 128 * 64 * 2;
static constexpr int S_AH = 0, S_AL = TILEB, S_BH = 2 * TILEB, S_BL = 3 * TILEB;
static constexpr int STAGEB = 4 * TILEB;
static constexpr int GEMM_SMEM = 2 * STAGEB;

__device__ __forceinline__ void tile_cpa(const bf16* __restrict__ g,
                                         int row0, int stride, int k0,
                                         uint32_t sdst, int tid) {
#pragma unroll
    for (int i = 0; i < 4; i++) {
        int idx = i * 256 + tid;
        int r = idx >> 3, c = idx & 7;
        const bf16* src = g + (size_t)(row0 + r) * stride + k0 + c * 8;
        CPA(sdst + swz(r * 128 + c * 16), src);
    }
}

__global__ __launch_bounds__(256, 1) void gemm_mma_kernel(
    const bf16* __restrict__ Ah, const bf16* __restrict__ Al,
    const bf16* __restrict__ Bh, const bf16* __restrict__ Bl,
    const float* __restrict__ bias, const float* __restrict__ r1,
    const float* __restrict__ r2, float* __restrict__ C,
    bf16* __restrict__ Ch, bf16* __restrict__ Cl,
    int NN, int KK, int act) {
    extern __shared__ char smem[];
    const uint32_t sb = smem_u32(smem);
    const int tid = threadIdx.x;
    const int wid = tid >> 5, lane = tid & 31;
    const int wm = wid >> 2, wn = wid & 3;
    const int rowBase = blockIdx.y * 128, colBase = blockIdx.x * 128;

    float acc[4][4][4];
#pragma unroll
    for (int i = 0; i < 4; i++)
#pragma unroll
        for (int j = 0; j < 4; j++)
#pragma unroll
            for (int q = 0; q < 4; q++) acc[i][j][q] = 0.f;

    const uint32_t a_row = (uint32_t)((wm * 64 + (lane & 15)) * 128);
    const uint32_t a_col = (uint32_t)((lane >> 4) * 16);
    const uint32_t b_row0 = (uint32_t)((wn * 32 + (lane & 7) + ((lane >> 4) << 3)) * 128);
    const uint32_t b_col = (uint32_t)(((lane >> 3) & 1) * 16);

    const int nc = KK / 64;
    tile_cpa(Ah, rowBase, KK, 0, sb + S_AH, tid);
    tile_cpa(Al, rowBase, KK, 0, sb + S_AL, tid);
    tile_cpa(Bh, colBase, KK, 0, sb + S_BH, tid);
    tile_cpa(Bl, colBase, KK, 0, sb + S_BL, tid);
    CPA_COMMIT();

    for (int c = 0; c < nc; c++) {
        if (c + 1 < nc) {
            uint32_t st = sb + ((c + 1) & 1) * STAGEB;
            int k0 = (c + 1) * 64;
            tile_cpa(Ah, rowBase, KK, k0, st + S_AH, tid);
            tile_cpa(Al, rowBase, KK, k0, st + S_AL, tid);
            tile_cpa(Bh, colBase, KK, k0, st + S_BH, tid);
            tile_cpa(Bl, colBase, KK, k0, st + S_BL, tid);
            CPA_COMMIT();
            CPA_WAIT1();
        } else {
            CPA_WAIT0();
        }
        __syncthreads();
        uint32_t st = sb + (c & 1) * STAGEB;

#pragma unroll
        for (int ks = 0; ks < 4; ks++) {
            const uint32_t kb = ks * 32;
            uint32_t bh[2][4], bl[2][4];
#pragma unroll
            for (int g = 0; g < 2; g++) {
                uint32_t roff = b_row0 + (uint32_t)(g * 16 * 128);
                ldsm4(bh[g], st + S_BH + smx(roff, kb + b_col));
                ldsm4(bl[g], st + S_BL + smx(roff, kb + b_col));
            }
#pragma unroll
            for (int mi = 0; mi < 4; mi++) {
                uint32_t roff = a_row + (uint32_t)(mi * 16 * 128);
                uint32_t a_h[4], a_l[4];
                ldsm4(a_h, st + S_AH + smx(roff, kb + a_col));
                ldsm4(a_l, st + S_AL + smx(roff, kb + a_col));
#pragma unroll
                for (int nj = 0; nj < 4; nj++) {
                    int g = nj >> 1, o = (nj & 1) * 2;
                    uint32_t h0 = bh[g][o], h1 = bh[g][o + 1];
                    uint32_t l0 = bl[g][o], l1 = bl[g][o + 1];
                    mma16816(acc[mi][nj], a_h, h0, h1);
                    mma16816(acc[mi][nj], a_h, l0, l1);
                    mma16816(acc[mi][nj], a_l, h0, h1);
                }
            }
        }
        __syncthreads();
    }

    const int tq = lane >> 2, tr = lane & 3;
#pragma unroll
    for (int mi = 0; mi < 4; mi++) {
#pragma unroll
        for (int nj = 0; nj < 4; nj++) {
            int n = colBase + wn * 32 + nj * 8 + tr * 2;
            float2 bb = *(const float2*)(bias + n);
#pragma unroll
            for (int half = 0; half < 2; half++) {
                int m = rowBase + wm * 64 + mi * 16 + tq + half * 8;
                size_t base = (size_t)m * NN + n;
                float v0 = acc[mi][nj][half * 2 + 0] + bb.x;
                float v1 = acc[mi][nj][half * 2 + 1] + bb.y;
                if (act == 1) { v0 = v0 * normcdff(v0); v1 = v1 * normcdff(v1); }
                if (r1) { float2 q = *(const float2*)(r1 + base); v0 += q.x; v1 += q.y; }
                if (r2) { float2 q = *(const float2*)(r2 + base); v0 += q.x; v1 += q.y; }
                if (C) { float2 ov = {v0, v1}; *(float2*)(C + base) = ov; }
                if (Ch) {
                    bf16 h0 = __float2bfloat16(v0);
                    bf16 h1 = __float2bfloat16(v1);
                    *(__nv_bfloat162*)(Ch + base) = __nv_bfloat162(h0, h1);
                    *(__nv_bfloat162*)(Cl + base) = __nv_bfloat162(
                        __float2bfloat16(v0 - __bfloat162float(h0)),
                        __float2bfloat16(v1 - __bfloat162float(h1)));
                }
            }
        }
    }
}

// ---------------- tensor-core attention --------------------------------------
// Per CTA: (b, h, 32-query tile). 8 warps = 2 (m) x 4 (n).
// scores = (Qh+Ql)(Kh+Kl)^T * scale + bias  (3-term split, fp32 smem)
// softmax rows in smem, aw re-split to bf16 hi/lo, ctx = (AWh+AWl)(Vh+Vl).
static constexpr int QT = 32;
static constexpr int SCS2 = 520;                 // fp32/bf16 row stride (elements)
static constexpr int AO_Q   = 0;                 // qh 4096 | ql 4096
static constexpr int AO_KV  = 8192;              // 2 stages x (h 8192 | l 8192)
static constexpr int AO_SC  = 40960;             // 32*520*4 = 66560
static constexpr int AO_AWH = 107520;            // 32*520*2 = 33280
static constexpr int AO_AWL = 140800;            // 33280
static constexpr int ATTN_SMEM = 174080;

__device__ __forceinline__ void tile64_cpa(const bf16* __restrict__ g,
                                           int row0, uint32_t sdst, int tid) {
#pragma unroll
    for (int i = 0; i < 2; i++) {
        int idx = i * 256 + tid;            // 0..511
        int r = idx >> 3, c = idx & 7;
        CPA(sdst + swz(r * 128 + c * 16), g + (size_t)(row0 + r) * D_ + c * 8);
    }
}

__global__ __launch_bounds__(256, 1) void attn_mma_kernel(
    const bf16* __restrict__ Qh, const bf16* __restrict__ Ql,
    const bf16* __restrict__ Kh, const bf16* __restrict__ Kl,
    const bf16* __restrict__ Vh, const bf16* __restrict__ Vl,
    const float* __restrict__ bias,
    bf16* __restrict__ Ch, bf16* __restrict__ Cl) {
    extern __shared__ char smem[];
    const uint32_t sb = smem_u32(smem);
    const int tid = threadIdx.x;
    const int wid = tid >> 5, lane = tid & 31;
    const int wm = wid >> 2, wn = wid & 3;
    const int q0 = blockIdx.x * QT, h = blockIdx.y, b = blockIdx.z;
    const size_t bh_off = (size_t)(b * S_) * D_ + h * DH_;
    const int tq = lane >> 2, tr = lane & 3;

    // prologue: Q hi/lo (32x64) + K chunk 0 -> stage 0
    {
        int r = tid >> 3, c = tid & 7;
        CPA(sb + AO_Q + swz(r * 128 + c * 16),        Qh + bh_off + (size_t)(q0 + r) * D_ + c * 8);
        CPA(sb + AO_Q + 4096 + swz(r * 128 + c * 16), Ql + bh_off + (size_t)(q0 + r) * D_ + c * 8);
    }
    tile64_cpa(Kh + bh_off, 0, sb + AO_KV, tid);
    tile64_cpa(Kl + bh_off, 0, sb + AO_KV + 8192, tid);
    CPA_COMMIT();
    CPA_WAIT0();
    __syncthreads();

    // Q A-fragments (register-resident, 4 k-steps)
    uint32_t qfh[4][4], qfl[4][4];
    {
        uint32_t arow = (uint32_t)((wm * 16 + (lane & 15)) * 128);
        uint32_t acol = (uint32_t)((lane >> 4) * 16);
#pragma unroll
        for (int ks = 0; ks < 4; ks++) {
            ldsm4(qfh[ks], sb + AO_Q + smx(arow, ks * 32 + acol));
            ldsm4(qfl[ks], sb + AO_Q + 4096 + smx(arow, ks * 32 + acol));
        }
    }

    // -------- scores pass: 8 K-chunks of 64 ---------------------------------
    const uint32_t b_row = (uint32_t)((wn * 16 + (lane & 7) + ((lane >> 4) << 3)) * 128);
    const uint32_t b_col = (uint32_t)(((lane >> 3) & 1) * 16);
    for (int c = 0; c < 8; c++) {
        if (c < 7) {
            uint32_t st = sb + AO_KV + ((c + 1) & 1) * 16384;
            tile64_cpa(Kh + bh_off, (c + 1) * 64, st, tid);
            tile64_cpa(Kl + bh_off, (c + 1) * 64, st + 8192, tid);
            CPA_COMMIT();
            CPA_WAIT1();
        } else {
            CPA_WAIT0();
        }
        __syncthreads();
        uint32_t st = sb + AO_KV + (c & 1) * 16384;

        float acc[2][4] = {};
#pragma unroll
        for (int ks = 0; ks < 4; ks++) {
            uint32_t cb = ks * 32 + b_col;
            uint32_t kh4[4], kl4[4];
            ldsm4(kh4, st + smx(b_row, cb));
            ldsm4(kl4, st + 8192 + smx(b_row, cb));
#pragma unroll
            for (int nj = 0; nj < 2; nj++) {
                mma16816(acc[nj], qfh[ks], kh4[nj * 2], kh4[nj * 2 + 1]);
                mma16816(acc[nj], qfh[ks], kl4[nj * 2], kl4[nj * 2 + 1]);
                mma16816(acc[nj], qfl[ks], kh4[nj * 2], kh4[nj * 2 + 1]);
            }
        }
        // write scores with scale + relative-position bias
        float* sc = (float*)(smem + AO_SC);
#pragma unroll
        for (int nj = 0; nj < 2; nj++) {
            int kg = c * 64 + wn * 16 + nj * 8 + tr * 2;
#pragma unroll
            for (int half = 0; half < 2; half++) {
                int m = wm * 16 + tq + half * 8;
                int rel = (q0 + m) - kg + (P_ - 1);
                sc[m * SCS2 + kg]     = acc[nj][half * 2 + 0] * 0.125f + __ldg(&bias[rel * H_ + h]);
                sc[m * SCS2 + kg + 1] = acc[nj][half * 2 + 1] * 0.125f + __ldg(&bias[(rel - 1) * H_ + h]);
            }
        }
        __syncthreads();
    }

    // prefetch V chunk 0 -> stage 0 (overlaps softmax)
    tile64_cpa(Vh + bh_off, 0, sb + AO_KV, tid);
    tile64_cpa(Vl + bh_off, 0, sb + AO_KV + 8192, tid);
    CPA_COMMIT();

    // -------- softmax: 8 warps x 4 rows, then split aw to bf16 hi/lo --------
    {
        float* sc = (float*)(smem + AO_SC);
        bf16* awh = (bf16*)(smem + AO_AWH);
        bf16* awl = (bf16*)(smem + AO_AWL);
#pragma unroll
        for (int rr = 0; rr < 4; rr++) {
            int r = wid * 4 + rr;
            float* row = sc + r * SCS2;
            float mx = -1e30f;
            for (int cc = lane; cc < S_; cc += 32) mx = fmaxf(mx, row[cc]);
#pragma unroll
            for (int o = 16; o > 0; o >>= 1) mx = fmaxf(mx, __shfl_xor_sync(0xffffffffu, mx, o));
            float sum = 0.f;
            for (int cc = lane; cc < S_; cc += 32) {
                float e = expf(row[cc] - mx);
                row[cc] = e;
                sum += e;
            }
#pragma unroll
            for (int o = 16; o > 0; o >>= 1) sum += __shfl_xor_sync(0xffffffffu, sum, o);
            float inv = 1.0f / sum;
            for (int cc = lane; cc < S_; cc += 32) {
                float a = row[cc] * inv;
                bf16 hi = __float2bfloat16(a);
                awh[r * SCS2 + cc] = hi;
                awl[r * SCS2 + cc] = __float2bfloat16(a - __bfloat162float(hi));
            }
        }
    }
    __syncthreads();

    // -------- ctx pass: 8 V-chunks of 64 -------------------------------------
    float cacc[2][4] = {};
    const uint32_t aw_row = (uint32_t)((wm * 16 + (lane & 15)) * (SCS2 * 2));
    const uint32_t v_row = (uint32_t)(((lane & 7) + ((lane >> 3) & 1) * 8) * 128);
    const uint32_t v_col = (uint32_t)(wn * 32 + (lane >> 4) * 16);
    for (int c = 0; c < 8; c++) {
        if (c < 7) {
            uint32_t st = sb + AO_KV + ((c + 1) & 1) * 16384;
            tile64_cpa(Vh + bh_off, (c + 1) * 64, st, tid);
            tile64_cpa(Vl + bh_off, (c + 1) * 64, st + 8192, tid);
            CPA_COMMIT();
            CPA_WAIT1();
        } else {
            CPA_WAIT0();
        }
        __syncthreads();
        uint32_t st = sb + AO_KV + (c & 1) * 16384;

#pragma unroll
        for (int ks = 0; ks < 4; ks++) {
            uint32_t awoff = aw_row + (uint32_t)((c * 64 + ks * 16 + (lane >> 4) * 8) * 2);
            uint32_t ah4[4], al4[4];
            ldsm4(ah4, sb + AO_AWH + awoff);
            ldsm4(al4, sb + AO_AWL + awoff);
            uint32_t vro = v_row + (uint32_t)(ks * 16 * 128);
            uint32_t vh4[4], vl4[4];
            ldsm4t(vh4, st + smx(vro, v_col));
            ldsm4t(vl4, st + 8192 + smx(vro, v_col));
#pragma unroll
            for (int nj = 0; nj < 2; nj++) {
                mma16816(cacc[nj], ah4, vh4[nj * 2], vh4[nj * 2 + 1]);
                mma16816(cacc[nj], ah4, vl4[nj * 2], vl4[nj * 2 + 1]);
                mma16816(cacc[nj], al4, vh4[nj * 2], vh4[nj * 2 + 1]);
            }
        }
        __syncthreads();
    }

    // -------- epilogue: write ctx bf16 hi/lo ---------------------------------
#pragma unroll
    for (int nj = 0; nj < 2; nj++) {
        int n = wn * 16 + nj * 8 + tr * 2;
#pragma unroll
        for (int half = 0; half < 2; half++) {
            int m = wm * 16 + tq + half * 8;
            size_t gidx = (size_t)(b * S_ + q0 + m) * D_ + h * DH_ + n;
            float v0 = cacc[nj][half * 2 + 0];
            float v1 = cacc[nj][half * 2 + 1];
            bf16 h0 = __float2bfloat16(v0);
            bf16 h1 = __float2bfloat16(v1);
            *(__nv_bfloat162*)(Ch + gidx) = __nv_bfloat162(h0, h1);
            *(__nv_bfloat162*)(Cl + gidx) = __nv_bfloat162(
                __float2bfloat16(v0 - __bfloat162float(h0)),
                __float2bfloat16(v1 - __bfloat162float(h1)));
        }
    }
}

// ---------------- launch ----------------------------------------------------
extern "C" void kernel_launch(void* const* d_in, const int* in_sizes, int n_in,
                              void* d_out, int out_size) {
    (void)in_sizes; (void)n_in; (void)out_size;
    const float* x    = (const float*)d_in[0];
    const float* pe   = (const float*)d_in[1];
    const float* wq   = (const float*)d_in[2];
    const float* bq   = (const float*)d_in[3];
    const float* wk   = (const float*)d_in[4];
    const float* bk   = (const float*)d_in[5];
    const float* wv   = (const float*)d_in[6];
    const float* bv   = (const float*)d_in[7];
    const float* wo   = (const float*)d_in[8];
    const float* bo   = (const float*)d_in[9];
    const float* bt   = (const float*)d_in[10];
    const float* w1   = (const float*)d_in[11];
    const float* b1   = (const float*)d_in[12];
    const float* w2   = (const float*)d_in[13];
    const float* b2   = (const float*)d_in[14];
    const float* ln1g = (const float*)d_in[15];
    const float* ln1b = (const float*)d_in[16];
    const float* ln2g = (const float*)d_in[17];
    const float* ln2b = (const float*)d_in[18];
    float* out = (float*)d_out;

    float *hb, *o1;
    bf16 *xnh, *xnl, *qh, *ql, *kh, *kl, *vh, *vl, *cxh, *cxl, *f1h, *f1l;
    bf16 *wqh, *wql, *wkh, *wkl, *wvh, *wvl, *woh, *wol, *w1h, *w1l, *w2h, *w2l;
    cudaGetSymbolAddress((void**)&hb,  g_h);
    cudaGetSymbolAddress((void**)&o1,  g_out1);
    cudaGetSymbolAddress((void**)&xnh, g_xn_h);  cudaGetSymbolAddress((void**)&xnl, g_xn_l);
    cudaGetSymbolAddress((void**)&qh,  g_q_h);   cudaGetSymbolAddress((void**)&ql,  g_q_l);
    cudaGetSymbolAddress((void**)&kh,  g_k_h);   cudaGetSymbolAddress((void**)&kl,  g_k_l);
    cudaGetSymbolAddress((void**)&vh,  g_v_h);   cudaGetSymbolAddress((void**)&vl,  g_v_l);
    cudaGetSymbolAddress((void**)&cxh, g_ctx_h); cudaGetSymbolAddress((void**)&cxl, g_ctx_l);
    cudaGetSymbolAddress((void**)&f1h, g_f1_h);  cudaGetSymbolAddress((void**)&f1l, g_f1_l);
    cudaGetSymbolAddress((void**)&wqh, g_wqT_h); cudaGetSymbolAddress((void**)&wql, g_wqT_l);
    cudaGetSymbolAddress((void**)&wkh, g_wkT_h); cudaGetSymbolAddress((void**)&wkl, g_wkT_l);
    cudaGetSymbolAddress((void**)&wvh, g_wvT_h); cudaGetSymbolAddress((void**)&wvl, g_wvT_l);
    cudaGetSymbolAddress((void**)&woh, g_woT_h); cudaGetSymbolAddress((void**)&wol, g_woT_l);
    cudaGetSymbolAddress((void**)&w1h, g_w1T_h); cudaGetSymbolAddress((void**)&w1l, g_w1T_l);
    cudaGetSymbolAddress((void**)&w2h, g_w2T_h); cudaGetSymbolAddress((void**)&w2l, g_w2T_l);

    cudaFuncSetAttribute(attn_mma_kernel, cudaFuncAttributeMaxDynamicSharedMemorySize, ATTN_SMEM);
    cudaFuncSetAttribute(gemm_mma_kernel, cudaFuncAttributeMaxDynamicSharedMemorySize, GEMM_SMEM);

    addpe_kernel<<<(M_ * D_) / 256, 256>>>(x, pe, hb);
    {
        dim3 gdd(D_ / 32, D_ / 32, L_);
        wtrans_kernel<<<gdd, 256>>>(wq, wqh, wql, D_, D_);
        wtrans_kernel<<<gdd, 256>>>(wk, wkh, wkl, D_, D_);
        wtrans_kernel<<<gdd, 256>>>(wv, wvh, wvl, D_, D_);
        wtrans_kernel<<<gdd, 256>>>(wo, woh, wol, D_, D_);
        dim3 g1(F_ / 32, D_ / 32, L_);
        wtrans_kernel<<<g1, 256>>>(w1, w1h, w1l, D_, F_);
        dim3 g2(D_ / 32, F_ / 32, L_);
        wtrans_kernel<<<g2, 256>>>(w2, w2h, w2l, F_, D_);
    }

    dim3 gD(D_ / 128, M_ / 128);
    dim3 gF(F_ / 128, M_ / 128);
    dim3 gAttn(S_ / QT, H_, B_);

    for (int l = 0; l < L_; l++) {
        size_t oDD = (size_t)l * D_ * D_;
        size_t oDF = (size_t)l * D_ * F_;
        size_t oD  = (size_t)l * D_;
        size_t oF  = (size_t)l * F_;

        ln_kernel<<<M_, 256>>>(hb, ln1g + oD, ln1b + oD, xnh, xnl);
        gemm_mma_kernel<<<gD, 256, GEMM_SMEM>>>(xnh, xnl, wqh + oDD, wql + oDD,
            bq + oD, nullptr, nullptr, nullptr, qh, ql, D_, D_, 0);
        gemm_mma_kernel<<<gD, 256, GEMM_SMEM>>>(xnh, xnl, wkh + oDD, wkl + oDD,
            bk + oD, nullptr, nullptr, nullptr, kh, kl, D_, D_, 0);
        gemm_mma_kernel<<<gD, 256, GEMM_SMEM>>>(xnh, xnl, wvh + oDD, wvl + oDD,
            bv + oD, nullptr, nullptr, nullptr, vh, vl, D_, D_, 0);

        attn_mma_kernel<<<gAttn, 256, ATTN_SMEM>>>(qh, ql, kh, kl, vh, vl,
            bt + (size_t)l * (2 * P_ - 1) * H_, cxh, cxl);

        gemm_mma_kernel<<<gD, 256, GEMM_SMEM>>>(cxh, cxl, woh + oDD, wol + oDD,
            bo + oD, hb, nullptr, o1, nullptr, nullptr, D_, D_, 0);

        ln_kernel<<<M_, 256>>>(o1, ln2g + oD, ln2b + oD, xnh, xnl);
        gemm_mma_kernel<<<gF, 256, GEMM_SMEM>>>(xnh, xnl, w1h + oDF, w1l + oDF,
            b1 + oF, nullptr, nullptr, nullptr, f1h, f1l, F_, D_, 1);
        float* dst = (l == L_ - 1) ? out : hb;
        gemm_mma_kernel<<<gD, 256, GEMM_SMEM>>>(f1h, f1l, w2h + oDF, w2l + oDF,
            b2 + oD, o1, hb, dst, nullptr, nullptr, D_, F_, 0);
    }
}

// round 6
// speedup vs baseline: 3.4932x; 1.0254x over previous
#include <cuda_runtime.h>
#include <cuda_bf16.h>
#include <math.h>
#include <cstdint>

using bf16 = __nv_bfloat16;

static constexpr int L_ = 6, D_ = 1024, H_ = 16, F_ = 4096, S_ = 512, B_ = 16, P_ = 512;
static constexpr int DH_ = D_ / H_;          // 64
static constexpr int M_ = B_ * S_;           // 8192
static constexpr int D3 = 3 * D_;            // 3072 (fused qkv width)

// ---------------- scratch (device globals; no allocations allowed) ----------
__device__ __align__(16) float g_h[(size_t)M_ * D_];
__device__ __align__(16) float g_out1[(size_t)M_ * D_];

__device__ __align__(16) bf16 g_xn_h[(size_t)M_ * D_];
__device__ __align__(16) bf16 g_xn_l[(size_t)M_ * D_];
__device__ __align__(16) bf16 g_qkv_h[(size_t)M_ * D3];
__device__ __align__(16) bf16 g_qkv_l[(size_t)M_ * D3];
__device__ __align__(16) bf16 g_ctx_h[(size_t)M_ * D_];
__device__ __align__(16) bf16 g_ctx_l[(size_t)M_ * D_];
__device__ __align__(16) bf16 g_f1_h[(size_t)M_ * F_];
__device__ __align__(16) bf16 g_f1_l[(size_t)M_ * F_];

// transposed+split weights: [N,K] bf16 (qkv fused: rows 0..1023=q, ..k, ..v)
__device__ __align__(16) bf16 g_wqkvT_h[(size_t)L_ * D3 * D_];
__device__ __align__(16) bf16 g_wqkvT_l[(size_t)L_ * D3 * D_];
__device__ __align__(16) bf16 g_woT_h[(size_t)L_ * D_ * D_];
__device__ __align__(16) bf16 g_woT_l[(size_t)L_ * D_ * D_];
__device__ __align__(16) bf16 g_w1T_h[(size_t)L_ * D_ * F_];
__device__ __align__(16) bf16 g_w1T_l[(size_t)L_ * D_ * F_];
__device__ __align__(16) bf16 g_w2T_h[(size_t)L_ * F_ * D_];
__device__ __align__(16) bf16 g_w2T_l[(size_t)L_ * F_ * D_];
__device__ __align__(16) float g_bqkv[(size_t)L_ * D3];

// ---------------- PTX helpers (sm_80-era, legal on plain sm_103) -------------
__device__ __forceinline__ uint32_t smem_u32(const void* p) {
    uint32_t a;
    asm("{ .reg .u64 t; cvta.to.shared.u64 t, %1; cvt.u32.u64 %0, t; }" : "=r"(a) : "l"(p));
    return a;
}
__device__ __forceinline__ void ldsm4(uint32_t* r, uint32_t addr) {
    asm volatile("ldmatrix.sync.aligned.m8n8.x4.shared.b16 {%0,%1,%2,%3}, [%4];"
                 : "=r"(r[0]), "=r"(r[1]), "=r"(r[2]), "=r"(r[3]) : "r"(addr));
}
__device__ __forceinline__ void ldsm4t(uint32_t* r, uint32_t addr) {
    asm volatile("ldmatrix.sync.aligned.m8n8.x4.trans.shared.b16 {%0,%1,%2,%3}, [%4];"
                 : "=r"(r[0]), "=r"(r[1]), "=r"(r[2]), "=r"(r[3]) : "r"(addr));
}
__device__ __forceinline__ void mma16816(float* d, const uint32_t* a, uint32_t b0, uint32_t b1) {
    asm volatile("mma.sync.aligned.m16n8k16.row.col.f32.bf16.bf16.f32 "
                 "{%0,%1,%2,%3}, {%4,%5,%6,%7}, {%8,%9}, {%0,%1,%2,%3};"
                 : "+f"(d[0]), "+f"(d[1]), "+f"(d[2]), "+f"(d[3])
                 : "r"(a[0]), "r"(a[1]), "r"(a[2]), "r"(a[3]), "r"(b0), "r"(b1));
}
#define CPA(dst, src)  asm volatile("cp.async.cg.shared.global [%0], [%1], 16;" :: "r"(dst), "l"(src))
#define CPA_COMMIT()   asm volatile("cp.async.commit_group;" ::: "memory")
#define CPA_WAIT1()    asm volatile("cp.async.wait_group 1;" ::: "memory")
#define CPA_WAIT0()    asm volatile("cp.async.wait_group 0;" ::: "memory")

__device__ __forceinline__ uint32_t swz(uint32_t off) { return off ^ ((off >> 3) & 0x70); }
__device__ __forceinline__ uint32_t smx(uint32_t row_byte, uint32_t col_byte) {
    return row_byte + (col_byte ^ ((row_byte >> 3) & 0x70));
}

// ---------------- h = x + pe -------------------------------------------------
__global__ __launch_bounds__(256) void addpe_kernel(const float* __restrict__ x,
                                                    const float* __restrict__ pe,
                                                    float* __restrict__ h) {
    int i = blockIdx.x * 256 + threadIdx.x;
    h[i] = x[i] + pe[i & (S_ * D_ - 1)];
}

// ---------------- pack qkv bias: [L,3072] -------------------------------------
__global__ __launch_bounds__(256) void packb_kernel(const float* __restrict__ bq,
                                                    const float* __restrict__ bk,
                                                    const float* __restrict__ bv,
                                                    float* __restrict__ o) {
    int l = blockIdx.y;
    int i = blockIdx.x * 256 + threadIdx.x;
    o[(size_t)l * D3 + i]            = bq[l * D_ + i];
    o[(size_t)l * D3 + D_ + i]       = bk[l * D_ + i];
    o[(size_t)l * D3 + 2 * D_ + i]   = bv[l * D_ + i];
}

// ---------------- weight transpose + bf16 split: W[K,N] -> T[N,K] hi/lo -----
__global__ __launch_bounds__(256) void wtrans_kernel(const float* __restrict__ W,
                                                     bf16* __restrict__ Th,
                                                     bf16* __restrict__ Tl,
                                                     int K, int N, size_t out_ls) {
    __shared__ float t[32][33];
    size_t inoff  = (size_t)blockIdx.z * K * N;
    size_t outoff = (size_t)blockIdx.z * out_ls;
    int k0 = blockIdx.y * 32, n0 = blockIdx.x * 32;
    int tx = threadIdx.x & 31, ty = threadIdx.x >> 5;
#pragma unroll
    for (int i = 0; i < 32; i += 8)
        t[ty + i][tx] = W[inoff + (size_t)(k0 + ty + i) * N + n0 + tx];
    __syncthreads();
#pragma unroll
    for (int i = 0; i < 32; i += 8) {
        float v = t[tx][ty + i];
        bf16 hi = __float2bfloat16(v);
        size_t idx = outoff + (size_t)(n0 + ty + i) * K + k0 + tx;
        Th[idx] = hi;
        Tl[idx] = __float2bfloat16(v - __bfloat162float(hi));
    }
}

// ---------------- LayerNorm: fp32 in -> bf16 hi/lo out -----------------------
__global__ __launch_bounds__(256) void ln_kernel(const float* __restrict__ x,
                                                 const float* __restrict__ g,
                                                 const float* __restrict__ b,
                                                 bf16* __restrict__ yh,
                                                 bf16* __restrict__ yl) {
    int row = blockIdx.x, tid = threadIdx.x;
    const float* xr = x + (size_t)row * D_;
    float4 f = *(const float4*)(xr + tid * 4);
    float s  = f.x + f.y + f.z + f.w;
    float ss = f.x * f.x + f.y * f.y + f.z * f.z + f.w * f.w;
#pragma unroll
    for (int o = 16; o > 0; o >>= 1) {
        s  += __shfl_xor_sync(0xffffffffu, s, o);
        ss += __shfl_xor_sync(0xffffffffu, ss, o);
    }
    __shared__ float rs[8], rss[8];
    if ((tid & 31) == 0) { rs[tid >> 5] = s; rss[tid >> 5] = ss; }
    __syncthreads();
    float ts = 0.f, tss = 0.f;
#pragma unroll
    for (int i = 0; i < 8; i++) { ts += rs[i]; tss += rss[i]; }
    float mean = ts * (1.0f / D_);
    float var  = tss * (1.0f / D_) - mean * mean;
    float r    = rsqrtf(var + 1e-6f);
    float4 g4 = *(const float4*)(g + tid * 4);
    float4 b4 = *(const float4*)(b + tid * 4);
    float o[4];
    o[0] = (f.x - mean) * r * g4.x + b4.x;
    o[1] = (f.y - mean) * r * g4.y + b4.y;
    o[2] = (f.z - mean) * r * g4.z + b4.z;
    o[3] = (f.w - mean) * r * g4.w + b4.w;
    size_t base = (size_t)row * D_ + tid * 4;
#pragma unroll
    for (int j = 0; j < 4; j += 2) {
        bf16 h0 = __float2bfloat16(o[j]);
        bf16 h1 = __float2bfloat16(o[j + 1]);
        *(__nv_bfloat162*)(yh + base + j) = __nv_bfloat162(h0, h1);
        *(__nv_bfloat162*)(yl + base + j) = __nv_bfloat162(
            __float2bfloat16(o[j] - __bfloat162float(h0)),
            __float2bfloat16(o[j + 1] - __bfloat162float(h1)));
    }
}

// ---------------- split-bf16 mma.sync GEMM 128x128, Kc=64, cp.async x3 ------
static constexpr int TILEB = 128 * 64 * 2;
static constexpr int S_AH = 0, S_AL = TILEB, S_BH = 2 * TILEB, S_BL = 3 * TILEB;
static constexpr int STAGEB = 4 * TILEB;        // 64 KB
static constexpr int GEMM_SMEM = 3 * STAGEB;    // 192 KB

__device__ __forceinline__ void tile_cpa(const bf16* __restrict__ g,
                                         int row0, int stride, int k0,
                                         uint32_t sdst, int tid) {
#pragma unroll
    for (int i = 0; i < 4; i++) {
        int idx = i * 256 + tid;
        int r = idx >> 3, c = idx & 7;
        const bf16* src = g + (size_t)(row0 + r) * stride + k0 + c * 8;
        CPA(sdst + swz(r * 128 + c * 16), src);
    }
}

__global__ __launch_bounds__(256, 1) void gemm_mma_kernel(
    const bf16* __restrict__ Ah, const bf16* __restrict__ Al,
    const bf16* __restrict__ Bh, const bf16* __restrict__ Bl,
    const float* __restrict__ bias, const float* __restrict__ r1,
    const float* __restrict__ r2, float* __restrict__ C,
    bf16* __restrict__ Ch, bf16* __restrict__ Cl,
    int NN, int KK, int act) {
    extern __shared__ char smem[];
    const uint32_t sb = smem_u32(smem);
    const int tid = threadIdx.x;
    const int wid = tid >> 5, lane = tid & 31;
    const int wm = wid >> 2, wn = wid & 3;
    const int rowBase = blockIdx.y * 128, colBase = blockIdx.x * 128;

    float acc[4][4][4];
#pragma unroll
    for (int i = 0; i < 4; i++)
#pragma unroll
        for (int j = 0; j < 4; j++)
#pragma unroll
            for (int q = 0; q < 4; q++) acc[i][j][q] = 0.f;

    const uint32_t a_row = (uint32_t)((wm * 64 + (lane & 15)) * 128);
    const uint32_t a_col = (uint32_t)((lane >> 4) * 16);
    const uint32_t b_row0 = (uint32_t)((wn * 32 + (lane & 7) + ((lane >> 4) << 3)) * 128);
    const uint32_t b_col = (uint32_t)(((lane >> 3) & 1) * 16);

    const int nc = KK / 64;
    // prologue: stages 0,1
    tile_cpa(Ah, rowBase, KK, 0, sb + S_AH, tid);
    tile_cpa(Al, rowBase, KK, 0, sb + S_AL, tid);
    tile_cpa(Bh, colBase, KK, 0, sb + S_BH, tid);
    tile_cpa(Bl, colBase, KK, 0, sb + S_BL, tid);
    CPA_COMMIT();
    {
        uint32_t st = sb + STAGEB;
        tile_cpa(Ah, rowBase, KK, 64, st + S_AH, tid);
        tile_cpa(Al, rowBase, KK, 64, st + S_AL, tid);
        tile_cpa(Bh, colBase, KK, 64, st + S_BH, tid);
        tile_cpa(Bl, colBase, KK, 64, st + S_BL, tid);
    }
    CPA_COMMIT();

    for (int c = 0; c < nc; c++) {
        if (c + 1 < nc) CPA_WAIT1(); else CPA_WAIT0();
        __syncthreads();
        if (c + 2 < nc) {
            uint32_t st = sb + ((c + 2) % 3) * STAGEB;
            int k0 = (c + 2) * 64;
            tile_cpa(Ah, rowBase, KK, k0, st + S_AH, tid);
            tile_cpa(Al, rowBase, KK, k0, st + S_AL, tid);
            tile_cpa(Bh, colBase, KK, k0, st + S_BH, tid);
            tile_cpa(Bl, colBase, KK, k0, st + S_BL, tid);
            CPA_COMMIT();
        }
        uint32_t st = sb + (c % 3) * STAGEB;

#pragma unroll
        for (int ks = 0; ks < 4; ks++) {
            const uint32_t kb = ks * 32;
            uint32_t bh[2][4], bl[2][4];
#pragma unroll
            for (int g = 0; g < 2; g++) {
                uint32_t roff = b_row0 + (uint32_t)(g * 16 * 128);
                ldsm4(bh[g], st + S_BH + smx(roff, kb + b_col));
                ldsm4(bl[g], st + S_BL + smx(roff, kb + b_col));
            }
#pragma unroll
            for (int mi = 0; mi < 4; mi++) {
                uint32_t roff = a_row + (uint32_t)(mi * 16 * 128);
                uint32_t a_h[4], a_l[4];
                ldsm4(a_h, st + S_AH + smx(roff, kb + a_col));
                ldsm4(a_l, st + S_AL + smx(roff, kb + a_col));
#pragma unroll
                for (int nj = 0; nj < 4; nj++) {
                    int g = nj >> 1, o = (nj & 1) * 2;
                    uint32_t h0 = bh[g][o], h1 = bh[g][o + 1];
                    uint32_t l0 = bl[g][o], l1 = bl[g][o + 1];
                    mma16816(acc[mi][nj], a_h, h0, h1);
                    mma16816(acc[mi][nj], a_h, l0, l1);
                    mma16816(acc[mi][nj], a_l, h0, h1);
                }
            }
        }
    }

    const int tq = lane >> 2, tr = lane & 3;
#pragma unroll
    for (int mi = 0; mi < 4; mi++) {
#pragma unroll
        for (int nj = 0; nj < 4; nj++) {
            int n = colBase + wn * 32 + nj * 8 + tr * 2;
            float2 bb = *(const float2*)(bias + n);
#pragma unroll
            for (int half = 0; half < 2; half++) {
                int m = rowBase + wm * 64 + mi * 16 + tq + half * 8;
                size_t base = (size_t)m * NN + n;
                float v0 = acc[mi][nj][half * 2 + 0] + bb.x;
                float v1 = acc[mi][nj][half * 2 + 1] + bb.y;
                if (act == 1) { v0 = v0 * normcdff(v0); v1 = v1 * normcdff(v1); }
                if (r1) { float2 q = *(const float2*)(r1 + base); v0 += q.x; v1 += q.y; }
                if (r2) { float2 q = *(const float2*)(r2 + base); v0 += q.x; v1 += q.y; }
                if (C) { float2 ov = {v0, v1}; *(float2*)(C + base) = ov; }
                if (Ch) {
                    bf16 h0 = __float2bfloat16(v0);
                    bf16 h1 = __float2bfloat16(v1);
                    *(__nv_bfloat162*)(Ch + base) = __nv_bfloat162(h0, h1);
                    *(__nv_bfloat162*)(Cl + base) = __nv_bfloat162(
                        __float2bfloat16(v0 - __bfloat162float(h0)),
                        __float2bfloat16(v1 - __bfloat162float(h1)));
                }
            }
        }
    }
}

// ---------------- tensor-core attention (reads fused qkv buffer) ------------
static constexpr int QT = 32;
static constexpr int SCS2 = 520;
static constexpr int AO_Q   = 0;
static constexpr int AO_KV  = 8192;
static constexpr int AO_SC  = 40960;
static constexpr int AO_AWH = 107520;
static constexpr int AO_AWL = 140800;
static constexpr int ATTN_SMEM = 174080;

__device__ __forceinline__ void tile64_cpa(const bf16* __restrict__ g,
                                           int row0, int stride,
                                           uint32_t sdst, int tid) {
#pragma unroll
    for (int i = 0; i < 2; i++) {
        int idx = i * 256 + tid;
        int r = idx >> 3, c = idx & 7;
        CPA(sdst + swz(r * 128 + c * 16), g + (size_t)(row0 + r) * stride + c * 8);
    }
}

__global__ __launch_bounds__(256, 1) void attn_mma_kernel(
    const bf16* __restrict__ qkvh, const bf16* __restrict__ qkvl,
    const float* __restrict__ bias,
    bf16* __restrict__ Ch, bf16* __restrict__ Cl) {
    extern __shared__ char smem[];
    const uint32_t sb = smem_u32(smem);
    const int tid = threadIdx.x;
    const int wid = tid >> 5, lane = tid & 31;
    const int wm = wid >> 2, wn = wid & 3;
    const int q0 = blockIdx.x * QT, h = blockIdx.y, b = blockIdx.z;
    const size_t base3 = (size_t)(b * S_) * D3 + h * DH_;
    const bf16* Qh = qkvh + base3;            const bf16* Ql = qkvl + base3;
    const bf16* Kh = qkvh + base3 + D_;       const bf16* Kl = qkvl + base3 + D_;
    const bf16* Vh = qkvh + base3 + 2 * D_;   const bf16* Vl = qkvl + base3 + 2 * D_;
    const int tq = lane >> 2, tr = lane & 3;

    // prologue: Q hi/lo (32x64) + K chunk 0 -> stage 0
    {
        int r = tid >> 3, c = tid & 7;
        CPA(sb + AO_Q + swz(r * 128 + c * 16),        Qh + (size_t)(q0 + r) * D3 + c * 8);
        CPA(sb + AO_Q + 4096 + swz(r * 128 + c * 16), Ql + (size_t)(q0 + r) * D3 + c * 8);
    }
    tile64_cpa(Kh, 0, D3, sb + AO_KV, tid);
    tile64_cpa(Kl, 0, D3, sb + AO_KV + 8192, tid);
    CPA_COMMIT();
    CPA_WAIT0();
    __syncthreads();

    uint32_t qfh[4][4], qfl[4][4];
    {
        uint32_t arow = (uint32_t)((wm * 16 + (lane & 15)) * 128);
        uint32_t acol = (uint32_t)((lane >> 4) * 16);
#pragma unroll
        for (int ks = 0; ks < 4; ks++) {
            ldsm4(qfh[ks], sb + AO_Q + smx(arow, ks * 32 + acol));
            ldsm4(qfl[ks], sb + AO_Q + 4096 + smx(arow, ks * 32 + acol));
        }
    }

    const uint32_t b_row = (uint32_t)((wn * 16 + (lane & 7) + ((lane >> 4) << 3)) * 128);
    const uint32_t b_col = (uint32_t)(((lane >> 3) & 1) * 16);
    for (int c = 0; c < 8; c++) {
        if (c < 7) {
            uint32_t st = sb + AO_KV + ((c + 1) & 1) * 16384;
            tile64_cpa(Kh, (c + 1) * 64, D3, st, tid);
            tile64_cpa(Kl, (c + 1) * 64, D3, st + 8192, tid);
            CPA_COMMIT();
            CPA_WAIT1();
        } else {
            CPA_WAIT0();
        }
        __syncthreads();
        uint32_t st = sb + AO_KV + (c & 1) * 16384;

        float acc[2][4] = {};
#pragma unroll
        for (int ks = 0; ks < 4; ks++) {
            uint32_t cb = ks * 32 + b_col;
            uint32_t kh4[4], kl4[4];
            ldsm4(kh4, st + smx(b_row, cb));
            ldsm4(kl4, st + 8192 + smx(b_row, cb));
#pragma unroll
            for (int nj = 0; nj < 2; nj++) {
                mma16816(acc[nj], qfh[ks], kh4[nj * 2], kh4[nj * 2 + 1]);
                mma16816(acc[nj], qfh[ks], kl4[nj * 2], kl4[nj * 2 + 1]);
                mma16816(acc[nj], qfl[ks], kh4[nj * 2], kh4[nj * 2 + 1]);
            }
        }
        float* sc = (float*)(smem + AO_SC);
#pragma unroll
        for (int nj = 0; nj < 2; nj++) {
            int kg = c * 64 + wn * 16 + nj * 8 + tr * 2;
#pragma unroll
            for (int half = 0; half < 2; half++) {
                int m = wm * 16 + tq + half * 8;
                int rel = (q0 + m) - kg + (P_ - 1);
                sc[m * SCS2 + kg]     = acc[nj][half * 2 + 0] * 0.125f + __ldg(&bias[rel * H_ + h]);
                sc[m * SCS2 + kg + 1] = acc[nj][half * 2 + 1] * 0.125f + __ldg(&bias[(rel - 1) * H_ + h]);
            }
        }
        __syncthreads();
    }

    tile64_cpa(Vh, 0, D3, sb + AO_KV, tid);
    tile64_cpa(Vl, 0, D3, sb + AO_KV + 8192, tid);
    CPA_COMMIT();

    {
        float* sc = (float*)(smem + AO_SC);
        bf16* awh = (bf16*)(smem + AO_AWH);
        bf16* awl = (bf16*)(smem + AO_AWL);
#pragma unroll
        for (int rr = 0; rr < 4; rr++) {
            int r = wid * 4 + rr;
            float* row = sc + r * SCS2;
            float mx = -1e30f;
            for (int cc = lane; cc < S_; cc += 32) mx = fmaxf(mx, row[cc]);
#pragma unroll
            for (int o = 16; o > 0; o >>= 1) mx = fmaxf(mx, __shfl_xor_sync(0xffffffffu, mx, o));
            float sum = 0.f;
            for (int cc = lane; cc < S_; cc += 32) {
                float e = expf(row[cc] - mx);
                row[cc] = e;
                sum += e;
            }
#pragma unroll
            for (int o = 16; o > 0; o >>= 1) sum += __shfl_xor_sync(0xffffffffu, sum, o);
            float inv = 1.0f / sum;
            for (int cc = lane; cc < S_; cc += 32) {
                float a = row[cc] * inv;
                bf16 hi = __float2bfloat16(a);
                awh[r * SCS2 + cc] = hi;
                awl[r * SCS2 + cc] = __float2bfloat16(a - __bfloat162float(hi));
            }
        }
    }
    __syncthreads();

    float cacc[2][4] = {};
    const uint32_t aw_row = (uint32_t)((wm * 16 + (lane & 15)) * (SCS2 * 2));
    const uint32_t v_row = (uint32_t)(((lane & 7) + ((lane >> 3) & 1) * 8) * 128);
    const uint32_t v_col = (uint32_t)(wn * 32 + (lane >> 4) * 16);
    for (int c = 0; c < 8; c++) {
        if (c < 7) {
            uint32_t st = sb + AO_KV + ((c + 1) & 1) * 16384;
            tile64_cpa(Vh, (c + 1) * 64, D3, st, tid);
            tile64_cpa(Vl, (c + 1) * 64, D3, st + 8192, tid);
            CPA_COMMIT();
            CPA_WAIT1();
        } else {
            CPA_WAIT0();
        }
        __syncthreads();
        uint32_t st = sb + AO_KV + (c & 1) * 16384;

#pragma unroll
        for (int ks = 0; ks < 4; ks++) {
            uint32_t awoff = aw_row + (uint32_t)((c * 64 + ks * 16 + (lane >> 4) * 8) * 2);
            uint32_t ah4[4], al4[4];
            ldsm4(ah4, sb + AO_AWH + awoff);
            ldsm4(al4, sb + AO_AWL + awoff);
            uint32_t vro = v_row + (uint32_t)(ks * 16 * 128);
            uint32_t vh4[4], vl4[4];
            ldsm4t(vh4, st + smx(vro, v_col));
            ldsm4t(vl4, st + 8192 + smx(vro, v_col));
#pragma unroll
            for (int nj = 0; nj < 2; nj++) {
                mma16816(cacc[nj], ah4, vh4[nj * 2], vh4[nj * 2 + 1]);
                mma16816(cacc[nj], ah4, vl4[nj * 2], vl4[nj * 2 + 1]);
                mma16816(cacc[nj], al4, vh4[nj * 2], vh4[nj * 2 + 1]);
            }
        }
        __syncthreads();
    }

#pragma unroll
    for (int nj = 0; nj < 2; nj++) {
        int n = wn * 16 + nj * 8 + tr * 2;
#pragma unroll
        for (int half = 0; half < 2; half++) {
            int m = wm * 16 + tq + half * 8;
            size_t gidx = (size_t)(b * S_ + q0 + m) * D_ + h * DH_ + n;
            float v0 = cacc[nj][half * 2 + 0];
            float v1 = cacc[nj][half * 2 + 1];
            bf16 h0 = __float2bfloat16(v0);
            bf16 h1 = __float2bfloat16(v1);
            *(__nv_bfloat162*)(Ch + gidx) = __nv_bfloat162(h0, h1);
            *(__nv_bfloat162*)(Cl + gidx) = __nv_bfloat162(
                __float2bfloat16(v0 - __bfloat162float(h0)),
                __float2bfloat16(v1 - __bfloat162float(h1)));
        }
    }
}

// ---------------- launch ----------------------------------------------------
extern "C" void kernel_launch(void* const* d_in, const int* in_sizes, int n_in,
                              void* d_out, int out_size) {
    (void)in_sizes; (void)n_in; (void)out_size;
    const float* x    = (const float*)d_in[0];
    const float* pe   = (const float*)d_in[1];
    const float* wq   = (const float*)d_in[2];
    const float* bq   = (const float*)d_in[3];
    const float* wk   = (const float*)d_in[4];
    const float* bk   = (const float*)d_in[5];
    const float* wv   = (const float*)d_in[6];
    const float* bv   = (const float*)d_in[7];
    const float* wo   = (const float*)d_in[8];
    const float* bo   = (const float*)d_in[9];
    const float* bt   = (const float*)d_in[10];
    const float* w1   = (const float*)d_in[11];
    const float* b1   = (const float*)d_in[12];
    const float* w2   = (const float*)d_in[13];
    const float* b2   = (const float*)d_in[14];
    const float* ln1g = (const float*)d_in[15];
    const float* ln1b = (const float*)d_in[16];
    const float* ln2g = (const float*)d_in[17];
    const float* ln2b = (const float*)d_in[18];
    float* out = (float*)d_out;

    float *hb, *o1, *bqkv;
    bf16 *xnh, *xnl, *qkvh, *qkvl, *cxh, *cxl, *f1h, *f1l;
    bf16 *wqkvhp, *wqkvlp, *woh, *wol, *w1h, *w1l, *w2h, *w2l;
    cudaGetSymbolAddress((void**)&hb,   g_h);
    cudaGetSymbolAddress((void**)&o1,   g_out1);
    cudaGetSymbolAddress((void**)&bqkv, g_bqkv);
    cudaGetSymbolAddress((void**)&xnh,  g_xn_h);  cudaGetSymbolAddress((void**)&xnl, g_xn_l);
    cudaGetSymbolAddress((void**)&qkvh, g_qkv_h); cudaGetSymbolAddress((void**)&qkvl, g_qkv_l);
    cudaGetSymbolAddress((void**)&cxh,  g_ctx_h); cudaGetSymbolAddress((void**)&cxl, g_ctx_l);
    cudaGetSymbolAddress((void**)&f1h,  g_f1_h);  cudaGetSymbolAddress((void**)&f1l, g_f1_l);
    cudaGetSymbolAddress((void**)&wqkvhp, g_wqkvT_h); cudaGetSymbolAddress((void**)&wqkvlp, g_wqkvT_l);
    cudaGetSymbolAddress((void**)&woh,  g_woT_h); cudaGetSymbolAddress((void**)&wol, g_woT_l);
    cudaGetSymbolAddress((void**)&w1h,  g_w1T_h); cudaGetSymbolAddress((void**)&w1l, g_w1T_l);
    cudaGetSymbolAddress((void**)&w2h,  g_w2T_h); cudaGetSymbolAddress((void**)&w2l, g_w2T_l);

    cudaFuncSetAttribute(attn_mma_kernel, cudaFuncAttributeMaxDynamicSharedMemorySize, ATTN_SMEM);
    cudaFuncSetAttribute(gemm_mma_kernel, cudaFuncAttributeMaxDynamicSharedMemorySize, GEMM_SMEM);

    addpe_kernel<<<(M_ * D_) / 256, 256>>>(x, pe, hb);
    packb_kernel<<<dim3(D_ / 256, L_), 256>>>(bq, bk, bv, bqkv);
    {
        const size_t DD = (size_t)D_ * D_;
        dim3 gdd(D_ / 32, D_ / 32, L_);
        wtrans_kernel<<<gdd, 256>>>(wq, wqkvhp,          wqkvlp,          D_, D_, (size_t)D3 * D_);
        wtrans_kernel<<<gdd, 256>>>(wk, wqkvhp + DD,     wqkvlp + DD,     D_, D_, (size_t)D3 * D_);
        wtrans_kernel<<<gdd, 256>>>(wv, wqkvhp + 2 * DD, wqkvlp + 2 * DD, D_, D_, (size_t)D3 * D_);
        wtrans_kernel<<<gdd, 256>>>(wo, woh, wol, D_, D_, DD);
        dim3 g1(F_ / 32, D_ / 32, L_);
        wtrans_kernel<<<g1, 256>>>(w1, w1h, w1l, D_, F_, (size_t)D_ * F_);
        dim3 g2(D_ / 32, F_ / 32, L_);
        wtrans_kernel<<<g2, 256>>>(w2, w2h, w2l, F_, D_, (size_t)F_ * D_);
    }

    dim3 gQKV(D3 / 128, M_ / 128);   // (24, 64)
    dim3 gD(D_ / 128, M_ / 128);     // (8, 64)
    dim3 gF(F_ / 128, M_ / 128);     // (32, 64)
    dim3 gAttn(S_ / QT, H_, B_);

    for (int l = 0; l < L_; l++) {
        size_t oQKV = (size_t)l * D3 * D_;
        size_t oDD  = (size_t)l * D_ * D_;
        size_t oDF  = (size_t)l * D_ * F_;
        size_t oD   = (size_t)l * D_;
        size_t oF   = (size_t)l * F_;

        ln_kernel<<<M_, 256>>>(hb, ln1g + oD, ln1b + oD, xnh, xnl);
        gemm_mma_kernel<<<gQKV, 256, GEMM_SMEM>>>(xnh, xnl, wqkvhp + oQKV, wqkvlp + oQKV,
            bqkv + (size_t)l * D3, nullptr, nullptr, nullptr, qkvh, qkvl, D3, D_, 0);

        attn_mma_kernel<<<gAttn, 256, ATTN_SMEM>>>(qkvh, qkvl,
            bt + (size_t)l * (2 * P_ - 1) * H_, cxh, cxl);

        gemm_mma_kernel<<<gD, 256, GEMM_SMEM>>>(cxh, cxl, woh + oDD, wol + oDD,
            bo + oD, hb, nullptr, o1, nullptr, nullptr, D_, D_, 0);

        ln_kernel<<<M_, 256>>>(o1, ln2g + oD, ln2b + oD, xnh, xnl);
        gemm_mma_kernel<<<gF, 256, GEMM_SMEM>>>(xnh, xnl, w1h + oDF, w1l + oDF,
            b1 + oF, nullptr, nullptr, nullptr, f1h, f1l, F_, D_, 1);
        float* dst = (l == L_ - 1) ? out : hb;
        gemm_mma_kernel<<<gD, 256, GEMM_SMEM>>>(f1h, f1l, w2h + oDF, w2l + oDF,
            b2 + oD, o1, hb, dst, nullptr, nullptr, D_, F_, 0);
    }
}

// round 7
// speedup vs baseline: 3.5768x; 1.0239x over previous
#include <cuda_runtime.h>
#include <cuda_bf16.h>
#include <math.h>
#include <cstdint>

using bf16 = __nv_bfloat16;

static constexpr int L_ = 6, D_ = 1024, H_ = 16, F_ = 4096, S_ = 512, B_ = 16, P_ = 512;
static constexpr int DH_ = D_ / H_;          // 64
static constexpr int M_ = B_ * S_;           // 8192
static constexpr int D3 = 3 * D_;            // 3072 (fused qkv width)

// ---------------- scratch (device globals; no allocations allowed) ----------
__device__ __align__(16) float g_h[(size_t)M_ * D_];
__device__ __align__(16) float g_out1[(size_t)M_ * D_];

__device__ __align__(16) bf16 g_xn_h[(size_t)M_ * D_];
__device__ __align__(16) bf16 g_xn_l[(size_t)M_ * D_];
__device__ __align__(16) bf16 g_qkv_h[(size_t)M_ * D3];
__device__ __align__(16) bf16 g_qkv_l[(size_t)M_ * D3];
__device__ __align__(16) bf16 g_ctx_h[(size_t)M_ * D_];
__device__ __align__(16) bf16 g_ctx_l[(size_t)M_ * D_];
__device__ __align__(16) bf16 g_f1_h[(size_t)M_ * F_];
__device__ __align__(16) bf16 g_f1_l[(size_t)M_ * F_];

// transposed+split weights: [N,K] bf16 (qkv fused: rows 0..1023=q, ..k, ..v)
__device__ __align__(16) bf16 g_wqkvT_h[(size_t)L_ * D3 * D_];
__device__ __align__(16) bf16 g_wqkvT_l[(size_t)L_ * D3 * D_];
__device__ __align__(16) bf16 g_woT_h[(size_t)L_ * D_ * D_];
__device__ __align__(16) bf16 g_woT_l[(size_t)L_ * D_ * D_];
__device__ __align__(16) bf16 g_w1T_h[(size_t)L_ * D_ * F_];
__device__ __align__(16) bf16 g_w1T_l[(size_t)L_ * D_ * F_];
__device__ __align__(16) bf16 g_w2T_h[(size_t)L_ * F_ * D_];
__device__ __align__(16) bf16 g_w2T_l[(size_t)L_ * F_ * D_];
__device__ __align__(16) float g_bqkv[(size_t)L_ * D3];

// ---------------- PTX helpers (sm_80-era, legal on plain sm_103) -------------
__device__ __forceinline__ uint32_t smem_u32(const void* p) {
    uint32_t a;
    asm("{ .reg .u64 t; cvta.to.shared.u64 t, %1; cvt.u32.u64 %0, t; }" : "=r"(a) : "l"(p));
    return a;
}
__device__ __forceinline__ void ldsm4(uint32_t* r, uint32_t addr) {
    asm volatile("ldmatrix.sync.aligned.m8n8.x4.shared.b16 {%0,%1,%2,%3}, [%4];"
                 : "=r"(r[0]), "=r"(r[1]), "=r"(r[2]), "=r"(r[3]) : "r"(addr));
}
__device__ __forceinline__ void ldsm4t(uint32_t* r, uint32_t addr) {
    asm volatile("ldmatrix.sync.aligned.m8n8.x4.trans.shared.b16 {%0,%1,%2,%3}, [%4];"
                 : "=r"(r[0]), "=r"(r[1]), "=r"(r[2]), "=r"(r[3]) : "r"(addr));
}
__device__ __forceinline__ void mma16816(float* d, const uint32_t* a, uint32_t b0, uint32_t b1) {
    asm volatile("mma.sync.aligned.m16n8k16.row.col.f32.bf16.bf16.f32 "
                 "{%0,%1,%2,%3}, {%4,%5,%6,%7}, {%8,%9}, {%0,%1,%2,%3};"
                 : "+f"(d[0]), "+f"(d[1]), "+f"(d[2]), "+f"(d[3])
                 : "r"(a[0]), "r"(a[1]), "r"(a[2]), "r"(a[3]), "r"(b0), "r"(b1));
}
#define CPA(dst, src)  asm volatile("cp.async.cg.shared.global [%0], [%1], 16;" :: "r"(dst), "l"(src))
#define CPA_COMMIT()   asm volatile("cp.async.commit_group;" ::: "memory")
#define CPA_WAIT1()    asm volatile("cp.async.wait_group 1;" ::: "memory")
#define CPA_WAIT0()    asm volatile("cp.async.wait_group 0;" ::: "memory")

__device__ __forceinline__ uint32_t swz(uint32_t off)   { return off ^ ((off >> 3) & 0x70); }
__device__ __forceinline__ uint32_t swz64(uint32_t off) { return off ^ ((off >> 3) & 0x30); }
__device__ __forceinline__ uint32_t smx(uint32_t row_byte, uint32_t col_byte) {
    return row_byte + (col_byte ^ ((row_byte >> 3) & 0x70));
}
__device__ __forceinline__ uint32_t smx64(uint32_t row_byte, uint32_t col_byte) {
    return row_byte + (col_byte ^ ((row_byte >> 3) & 0x30));
}

// ---------------- h = x + pe -------------------------------------------------
__global__ __launch_bounds__(256) void addpe_kernel(const float* __restrict__ x,
                                                    const float* __restrict__ pe,
                                                    float* __restrict__ h) {
    int i = blockIdx.x * 256 + threadIdx.x;
    h[i] = x[i] + pe[i & (S_ * D_ - 1)];
}

// ---------------- pack qkv bias: [L,3072] -------------------------------------
__global__ __launch_bounds__(256) void packb_kernel(const float* __restrict__ bq,
                                                    const float* __restrict__ bk,
                                                    const float* __restrict__ bv,
                                                    float* __restrict__ o) {
    int l = blockIdx.y;
    int i = blockIdx.x * 256 + threadIdx.x;
    o[(size_t)l * D3 + i]            = bq[l * D_ + i];
    o[(size_t)l * D3 + D_ + i]       = bk[l * D_ + i];
    o[(size_t)l * D3 + 2 * D_ + i]   = bv[l * D_ + i];
}

// ---------------- weight transpose + bf16 split: W[K,N] -> T[N,K] hi/lo -----
__global__ __launch_bounds__(256) void wtrans_kernel(const float* __restrict__ W,
                                                     bf16* __restrict__ Th,
                                                     bf16* __restrict__ Tl,
                                                     int K, int N, size_t out_ls) {
    __shared__ float t[32][33];
    size_t inoff  = (size_t)blockIdx.z * K * N;
    size_t outoff = (size_t)blockIdx.z * out_ls;
    int k0 = blockIdx.y * 32, n0 = blockIdx.x * 32;
    int tx = threadIdx.x & 31, ty = threadIdx.x >> 5;
#pragma unroll
    for (int i = 0; i < 32; i += 8)
        t[ty + i][tx] = W[inoff + (size_t)(k0 + ty + i) * N + n0 + tx];
    __syncthreads();
#pragma unroll
    for (int i = 0; i < 32; i += 8) {
        float v = t[tx][ty + i];
        bf16 hi = __float2bfloat16(v);
        size_t idx = outoff + (size_t)(n0 + ty + i) * K + k0 + tx;
        Th[idx] = hi;
        Tl[idx] = __float2bfloat16(v - __bfloat162float(hi));
    }
}

// ---------------- LayerNorm: fp32 in -> bf16 hi/lo out -----------------------
__global__ __launch_bounds__(256) void ln_kernel(const float* __restrict__ x,
                                                 const float* __restrict__ g,
                                                 const float* __restrict__ b,
                                                 bf16* __restrict__ yh,
                                                 bf16* __restrict__ yl) {
    int row = blockIdx.x, tid = threadIdx.x;
    const float* xr = x + (size_t)row * D_;
    float4 f = *(const float4*)(xr + tid * 4);
    float s  = f.x + f.y + f.z + f.w;
    float ss = f.x * f.x + f.y * f.y + f.z * f.z + f.w * f.w;
#pragma unroll
    for (int o = 16; o > 0; o >>= 1) {
        s  += __shfl_xor_sync(0xffffffffu, s, o);
        ss += __shfl_xor_sync(0xffffffffu, ss, o);
    }
    __shared__ float rs[8], rss[8];
    if ((tid & 31) == 0) { rs[tid >> 5] = s; rss[tid >> 5] = ss; }
    __syncthreads();
    float ts = 0.f, tss = 0.f;
#pragma unroll
    for (int i = 0; i < 8; i++) { ts += rs[i]; tss += rss[i]; }
    float mean = ts * (1.0f / D_);
    float var  = tss * (1.0f / D_) - mean * mean;
    float r    = rsqrtf(var + 1e-6f);
    float4 g4 = *(const float4*)(g + tid * 4);
    float4 b4 = *(const float4*)(b + tid * 4);
    float o[4];
    o[0] = (f.x - mean) * r * g4.x + b4.x;
    o[1] = (f.y - mean) * r * g4.y + b4.y;
    o[2] = (f.z - mean) * r * g4.z + b4.z;
    o[3] = (f.w - mean) * r * g4.w + b4.w;
    size_t base = (size_t)row * D_ + tid * 4;
#pragma unroll
    for (int j = 0; j < 4; j += 2) {
        bf16 h0 = __float2bfloat16(o[j]);
        bf16 h1 = __float2bfloat16(o[j + 1]);
        *(__nv_bfloat162*)(yh + base + j) = __nv_bfloat162(h0, h1);
        *(__nv_bfloat162*)(yl + base + j) = __nv_bfloat162(
            __float2bfloat16(o[j] - __bfloat162float(h0)),
            __float2bfloat16(o[j + 1] - __bfloat162float(h1)));
    }
}

// ---------------- split-bf16 mma.sync GEMM 128x128, Kc=32, SW64, x3, occ2 ---
static constexpr int TILE32 = 128 * 32 * 2;     // 8 KB per matrix tile
static constexpr int S_AH = 0, S_AL = TILE32, S_BH = 2 * TILE32, S_BL = 3 * TILE32;
static constexpr int STAGEB = 4 * TILE32;       // 32 KB per stage
static constexpr int GEMM_SMEM = 3 * STAGEB;    // 96 KB -> 2 CTAs/SM

__device__ __forceinline__ void tile_cpa32(const bf16* __restrict__ g,
                                           int row0, int stride, int k0,
                                           uint32_t sdst, int tid) {
#pragma unroll
    for (int i = 0; i < 2; i++) {
        int idx = i * 256 + tid;        // 0..511
        int r = idx >> 2, c = idx & 3;
        const bf16* src = g + (size_t)(row0 + r) * stride + k0 + c * 8;
        CPA(sdst + swz64(r * 64 + c * 16), src);
    }
}

__global__ __launch_bounds__(256, 2) void gemm_mma_kernel(
    const bf16* __restrict__ Ah, const bf16* __restrict__ Al,
    const bf16* __restrict__ Bh, const bf16* __restrict__ Bl,
    const float* __restrict__ bias, const float* __restrict__ r1,
    const float* __restrict__ r2, float* __restrict__ C,
    bf16* __restrict__ Ch, bf16* __restrict__ Cl,
    int NN, int KK, int act) {
    extern __shared__ char smem[];
    const uint32_t sb = smem_u32(smem);
    const int tid = threadIdx.x;
    const int wid = tid >> 5, lane = tid & 31;
    const int wm = wid >> 2, wn = wid & 3;
    const int rowBase = blockIdx.y * 128, colBase = blockIdx.x * 128;

    float acc[4][4][4];
#pragma unroll
    for (int i = 0; i < 4; i++)
#pragma unroll
        for (int j = 0; j < 4; j++)
#pragma unroll
            for (int q = 0; q < 4; q++) acc[i][j][q] = 0.f;

    // ldmatrix lane addressing (64-byte rows, SW64)
    const uint32_t a_row = (uint32_t)((wm * 64 + (lane & 15)) * 64);
    const uint32_t a_col = (uint32_t)((lane >> 4) * 16);
    const uint32_t b_row0 = (uint32_t)((wn * 32 + (lane & 7) + ((lane >> 4) << 3)) * 64);
    const uint32_t b_col = (uint32_t)(((lane >> 3) & 1) * 16);

    const int nc = KK / 32;
    // prologue: stages 0,1
    tile_cpa32(Ah, rowBase, KK, 0, sb + S_AH, tid);
    tile_cpa32(Al, rowBase, KK, 0, sb + S_AL, tid);
    tile_cpa32(Bh, colBase, KK, 0, sb + S_BH, tid);
    tile_cpa32(Bl, colBase, KK, 0, sb + S_BL, tid);
    CPA_COMMIT();
    {
        uint32_t st = sb + STAGEB;
        tile_cpa32(Ah, rowBase, KK, 32, st + S_AH, tid);
        tile_cpa32(Al, rowBase, KK, 32, st + S_AL, tid);
        tile_cpa32(Bh, colBase, KK, 32, st + S_BH, tid);
        tile_cpa32(Bl, colBase, KK, 32, st + S_BL, tid);
    }
    CPA_COMMIT();

    for (int c = 0; c < nc; c++) {
        if (c + 1 < nc) CPA_WAIT1(); else CPA_WAIT0();
        __syncthreads();
        if (c + 2 < nc) {
            uint32_t st = sb + ((c + 2) % 3) * STAGEB;
            int k0 = (c + 2) * 32;
            tile_cpa32(Ah, rowBase, KK, k0, st + S_AH, tid);
            tile_cpa32(Al, rowBase, KK, k0, st + S_AL, tid);
            tile_cpa32(Bh, colBase, KK, k0, st + S_BH, tid);
            tile_cpa32(Bl, colBase, KK, k0, st + S_BL, tid);
            CPA_COMMIT();
        }
        uint32_t st = sb + (c % 3) * STAGEB;

#pragma unroll
        for (int ks = 0; ks < 2; ks++) {
            const uint32_t kb = ks * 32;     // 16 bf16 = 32 bytes per k-step
            uint32_t bh[2][4], bl[2][4];
#pragma unroll
            for (int g = 0; g < 2; g++) {
                uint32_t roff = b_row0 + (uint32_t)(g * 16 * 64);
                ldsm4(bh[g], st + S_BH + smx64(roff, kb + b_col));
                ldsm4(bl[g], st + S_BL + smx64(roff, kb + b_col));
            }
#pragma unroll
            for (int mi = 0; mi < 4; mi++) {
                uint32_t roff = a_row + (uint32_t)(mi * 16 * 64);
                uint32_t a_h[4], a_l[4];
                ldsm4(a_h, st + S_AH + smx64(roff, kb + a_col));
                ldsm4(a_l, st + S_AL + smx64(roff, kb + a_col));
#pragma unroll
                for (int nj = 0; nj < 4; nj++) {
                    int g = nj >> 1, o = (nj & 1) * 2;
                    uint32_t h0 = bh[g][o], h1 = bh[g][o + 1];
                    uint32_t l0 = bl[g][o], l1 = bl[g][o + 1];
                    mma16816(acc[mi][nj], a_h, h0, h1);
                    mma16816(acc[mi][nj], a_h, l0, l1);
                    mma16816(acc[mi][nj], a_l, h0, h1);
                }
            }
        }
    }

    const int tq = lane >> 2, tr = lane & 3;
#pragma unroll
    for (int mi = 0; mi < 4; mi++) {
#pragma unroll
        for (int nj = 0; nj < 4; nj++) {
            int n = colBase + wn * 32 + nj * 8 + tr * 2;
            float2 bb = *(const float2*)(bias + n);
#pragma unroll
            for (int half = 0; half < 2; half++) {
                int m = rowBase + wm * 64 + mi * 16 + tq + half * 8;
                size_t base = (size_t)m * NN + n;
                float v0 = acc[mi][nj][half * 2 + 0] + bb.x;
                float v1 = acc[mi][nj][half * 2 + 1] + bb.y;
                if (act == 1) { v0 = v0 * normcdff(v0); v1 = v1 * normcdff(v1); }
                if (r1) { float2 q = *(const float2*)(r1 + base); v0 += q.x; v1 += q.y; }
                if (r2) { float2 q = *(const float2*)(r2 + base); v0 += q.x; v1 += q.y; }
                if (C) { float2 ov = {v0, v1}; *(float2*)(C + base) = ov; }
                if (Ch) {
                    bf16 h0 = __float2bfloat16(v0);
                    bf16 h1 = __float2bfloat16(v1);
                    *(__nv_bfloat162*)(Ch + base) = __nv_bfloat162(h0, h1);
                    *(__nv_bfloat162*)(Cl + base) = __nv_bfloat162(
                        __float2bfloat16(v0 - __bfloat162float(h0)),
                        __float2bfloat16(v1 - __bfloat162float(h1)));
                }
            }
        }
    }
}

// ---------------- tensor-core attention (reads fused qkv buffer) ------------
static constexpr int QT = 32;
static constexpr int SCS2 = 520;
static constexpr int AO_Q   = 0;
static constexpr int AO_KV  = 8192;
static constexpr int AO_SC  = 40960;
static constexpr int AO_AWH = 107520;
static constexpr int AO_AWL = 140800;
static constexpr int ATTN_SMEM = 174080;

__device__ __forceinline__ void tile64_cpa(const bf16* __restrict__ g,
                                           int row0, int stride,
                                           uint32_t sdst, int tid) {
#pragma unroll
    for (int i = 0; i < 2; i++) {
        int idx = i * 256 + tid;
        int r = idx >> 3, c = idx & 7;
        CPA(sdst + swz(r * 128 + c * 16), g + (size_t)(row0 + r) * stride + c * 8);
    }
}

__global__ __launch_bounds__(256, 1) void attn_mma_kernel(
    const bf16* __restrict__ qkvh, const bf16* __restrict__ qkvl,
    const float* __restrict__ bias,
    bf16* __restrict__ Ch, bf16* __restrict__ Cl) {
    extern __shared__ char smem[];
    const uint32_t sb = smem_u32(smem);
    const int tid = threadIdx.x;
    const int wid = tid >> 5, lane = tid & 31;
    const int wm = wid >> 2, wn = wid & 3;
    const int q0 = blockIdx.x * QT, h = blockIdx.y, b = blockIdx.z;
    const size_t base3 = (size_t)(b * S_) * D3 + h * DH_;
    const bf16* Qh = qkvh + base3;            const bf16* Ql = qkvl + base3;
    const bf16* Kh = qkvh + base3 + D_;       const bf16* Kl = qkvl + base3 + D_;
    const bf16* Vh = qkvh + base3 + 2 * D_;   const bf16* Vl = qkvl + base3 + 2 * D_;
    const int tq = lane >> 2, tr = lane & 3;

    {
        int r = tid >> 3, c = tid & 7;
        CPA(sb + AO_Q + swz(r * 128 + c * 16),        Qh + (size_t)(q0 + r) * D3 + c * 8);
        CPA(sb + AO_Q + 4096 + swz(r * 128 + c * 16), Ql + (size_t)(q0 + r) * D3 + c * 8);
    }
    tile64_cpa(Kh, 0, D3, sb + AO_KV, tid);
    tile64_cpa(Kl, 0, D3, sb + AO_KV + 8192, tid);
    CPA_COMMIT();
    CPA_WAIT0();
    __syncthreads();

    uint32_t qfh[4][4], qfl[4][4];
    {
        uint32_t arow = (uint32_t)((wm * 16 + (lane & 15)) * 128);
        uint32_t acol = (uint32_t)((lane >> 4) * 16);
#pragma unroll
        for (int ks = 0; ks < 4; ks++) {
            ldsm4(qfh[ks], sb + AO_Q + smx(arow, ks * 32 + acol));
            ldsm4(qfl[ks], sb + AO_Q + 4096 + smx(arow, ks * 32 + acol));
        }
    }

    const uint32_t b_row = (uint32_t)((wn * 16 + (lane & 7) + ((lane >> 4) << 3)) * 128);
    const uint32_t b_col = (uint32_t)(((lane >> 3) & 1) * 16);
    for (int c = 0; c < 8; c++) {
        if (c < 7) {
            uint32_t st = sb + AO_KV + ((c + 1) & 1) * 16384;
            tile64_cpa(Kh, (c + 1) * 64, D3, st, tid);
            tile64_cpa(Kl, (c + 1) * 64, D3, st + 8192, tid);
            CPA_COMMIT();
            CPA_WAIT1();
        } else {
            CPA_WAIT0();
        }
        __syncthreads();
        uint32_t st = sb + AO_KV + (c & 1) * 16384;

        float acc[2][4] = {};
#pragma unroll
        for (int ks = 0; ks < 4; ks++) {
            uint32_t cb = ks * 32 + b_col;
            uint32_t kh4[4], kl4[4];
            ldsm4(kh4, st + smx(b_row, cb));
            ldsm4(kl4, st + 8192 + smx(b_row, cb));
#pragma unroll
            for (int nj = 0; nj < 2; nj++) {
                mma16816(acc[nj], qfh[ks], kh4[nj * 2], kh4[nj * 2 + 1]);
                mma16816(acc[nj], qfh[ks], kl4[nj * 2], kl4[nj * 2 + 1]);
                mma16816(acc[nj], qfl[ks], kh4[nj * 2], kh4[nj * 2 + 1]);
            }
        }
        float* sc = (float*)(smem + AO_SC);
#pragma unroll
        for (int nj = 0; nj < 2; nj++) {
            int kg = c * 64 + wn * 16 + nj * 8 + tr * 2;
#pragma unroll
            for (int half = 0; half < 2; half++) {
                int m = wm * 16 + tq + half * 8;
                int rel = (q0 + m) - kg + (P_ - 1);
                sc[m * SCS2 + kg]     = acc[nj][half * 2 + 0] * 0.125f + __ldg(&bias[rel * H_ + h]);
                sc[m * SCS2 + kg + 1] = acc[nj][half * 2 + 1] * 0.125f + __ldg(&bias[(rel - 1) * H_ + h]);
            }
        }
        __syncthreads();
    }

    tile64_cpa(Vh, 0, D3, sb + AO_KV, tid);
    tile64_cpa(Vl, 0, D3, sb + AO_KV + 8192, tid);
    CPA_COMMIT();

    {
        float* sc = (float*)(smem + AO_SC);
        bf16* awh = (bf16*)(smem + AO_AWH);
        bf16* awl = (bf16*)(smem + AO_AWL);
#pragma unroll
        for (int rr = 0; rr < 4; rr++) {
            int r = wid * 4 + rr;
            float* row = sc + r * SCS2;
            float mx = -1e30f;
            for (int cc = lane; cc < S_; cc += 32) mx = fmaxf(mx, row[cc]);
#pragma unroll
            for (int o = 16; o > 0; o >>= 1) mx = fmaxf(mx, __shfl_xor_sync(0xffffffffu, mx, o));
            float sum = 0.f;
            for (int cc = lane; cc < S_; cc += 32) {
                float e = expf(row[cc] - mx);
                row[cc] = e;
                sum += e;
            }
#pragma unroll
            for (int o = 16; o > 0; o >>= 1) sum += __shfl_xor_sync(0xffffffffu, sum, o);
            float inv = 1.0f / sum;
            for (int cc = lane; cc < S_; cc += 32) {
                float a = row[cc] * inv;
                bf16 hi = __float2bfloat16(a);
                awh[r * SCS2 + cc] = hi;
                awl[r * SCS2 + cc] = __float2bfloat16(a - __bfloat162float(hi));
            }
        }
    }
    __syncthreads();

    float cacc[2][4] = {};
    const uint32_t aw_row = (uint32_t)((wm * 16 + (lane & 15)) * (SCS2 * 2));
    const uint32_t v_row = (uint32_t)(((lane & 7) + ((lane >> 3) & 1) * 8) * 128);
    const uint32_t v_col = (uint32_t)(wn * 32 + (lane >> 4) * 16);
    for (int c = 0; c < 8; c++) {
        if (c < 7) {
            uint32_t st = sb + AO_KV + ((c + 1) & 1) * 16384;
            tile64_cpa(Vh, (c + 1) * 64, D3, st, tid);
            tile64_cpa(Vl, (c + 1) * 64, D3, st + 8192, tid);
            CPA_COMMIT();
            CPA_WAIT1();
        } else {
            CPA_WAIT0();
        }
        __syncthreads();
        uint32_t st = sb + AO_KV + (c & 1) * 16384;

#pragma unroll
        for (int ks = 0; ks < 4; ks++) {
            uint32_t awoff = aw_row + (uint32_t)((c * 64 + ks * 16 + (lane >> 4) * 8) * 2);
            uint32_t ah4[4], al4[4];
            ldsm4(ah4, sb + AO_AWH + awoff);
            ldsm4(al4, sb + AO_AWL + awoff);
            uint32_t vro = v_row + (uint32_t)(ks * 16 * 128);
            uint32_t vh4[4], vl4[4];
            ldsm4t(vh4, st + smx(vro, v_col));
            ldsm4t(vl4, st + 8192 + smx(vro, v_col));
#pragma unroll
            for (int nj = 0; nj < 2; nj++) {
                mma16816(cacc[nj], ah4, vh4[nj * 2], vh4[nj * 2 + 1]);
                mma16816(cacc[nj], ah4, vl4[nj * 2], vl4[nj * 2 + 1]);
                mma16816(cacc[nj], al4, vh4[nj * 2], vh4[nj * 2 + 1]);
            }
        }
        __syncthreads();
    }

#pragma unroll
    for (int nj = 0; nj < 2; nj++) {
        int n = wn * 16 + nj * 8 + tr * 2;
#pragma unroll
        for (int half = 0; half < 2; half++) {
            int m = wm * 16 + tq + half * 8;
            size_t gidx = (size_t)(b * S_ + q0 + m) * D_ + h * DH_ + n;
            float v0 = cacc[nj][half * 2 + 0];
            float v1 = cacc[nj][half * 2 + 1];
            bf16 h0 = __float2bfloat16(v0);
            bf16 h1 = __float2bfloat16(v1);
            *(__nv_bfloat162*)(Ch + gidx) = __nv_bfloat162(h0, h1);
            *(__nv_bfloat162*)(Cl + gidx) = __nv_bfloat162(
                __float2bfloat16(v0 - __bfloat162float(h0)),
                __float2bfloat16(v1 - __bfloat162float(h1)));
        }
    }
}

// ---------------- launch ----------------------------------------------------
extern "C" void kernel_launch(void* const* d_in, const int* in_sizes, int n_in,
                              void* d_out, int out_size) {
    (void)in_sizes; (void)n_in; (void)out_size;
    const float* x    = (const float*)d_in[0];
    const float* pe   = (const float*)d_in[1];
    const float* wq   = (const float*)d_in[2];
    const float* bq   = (const float*)d_in[3];
    const float* wk   = (const float*)d_in[4];
    const float* bk   = (const float*)d_in[5];
    const float* wv   = (const float*)d_in[6];
    const float* bv   = (const float*)d_in[7];
    const float* wo   = (const float*)d_in[8];
    const float* bo   = (const float*)d_in[9];
    const float* bt   = (const float*)d_in[10];
    const float* w1   = (const float*)d_in[11];
    const float* b1   = (const float*)d_in[12];
    const float* w2   = (const float*)d_in[13];
    const float* b2   = (const float*)d_in[14];
    const float* ln1g = (const float*)d_in[15];
    const float* ln1b = (const float*)d_in[16];
    const float* ln2g = (const float*)d_in[17];
    const float* ln2b = (const float*)d_in[18];
    float* out = (float*)d_out;

    float *hb, *o1, *bqkv;
    bf16 *xnh, *xnl, *qkvh, *qkvl, *cxh, *cxl, *f1h, *f1l;
    bf16 *wqkvhp, *wqkvlp, *woh, *wol, *w1h, *w1l, *w2h, *w2l;
    cudaGetSymbolAddress((void**)&hb,   g_h);
    cudaGetSymbolAddress((void**)&o1,   g_out1);
    cudaGetSymbolAddress((void**)&bqkv, g_bqkv);
    cudaGetSymbolAddress((void**)&xnh,  g_xn_h);  cudaGetSymbolAddress((void**)&xnl, g_xn_l);
    cudaGetSymbolAddress((void**)&qkvh, g_qkv_h); cudaGetSymbolAddress((void**)&qkvl, g_qkv_l);
    cudaGetSymbolAddress((void**)&cxh,  g_ctx_h); cudaGetSymbolAddress((void**)&cxl, g_ctx_l);
    cudaGetSymbolAddress((void**)&f1h,  g_f1_h);  cudaGetSymbolAddress((void**)&f1l, g_f1_l);
    cudaGetSymbolAddress((void**)&wqkvhp, g_wqkvT_h); cudaGetSymbolAddress((void**)&wqkvlp, g_wqkvT_l);
    cudaGetSymbolAddress((void**)&woh,  g_woT_h); cudaGetSymbolAddress((void**)&wol, g_woT_l);
    cudaGetSymbolAddress((void**)&w1h,  g_w1T_h); cudaGetSymbolAddress((void**)&w1l, g_w1T_l);
    cudaGetSymbolAddress((void**)&w2h,  g_w2T_h); cudaGetSymbolAddress((void**)&w2l, g_w2T_l);

    cudaFuncSetAttribute(attn_mma_kernel, cudaFuncAttributeMaxDynamicSharedMemorySize, ATTN_SMEM);
    cudaFuncSetAttribute(gemm_mma_kernel, cudaFuncAttributeMaxDynamicSharedMemorySize, GEMM_SMEM);

    addpe_kernel<<<(M_ * D_) / 256, 256>>>(x, pe, hb);
    packb_kernel<<<dim3(D_ / 256, L_), 256>>>(bq, bk, bv, bqkv);
    {
        const size_t DD = (size_t)D_ * D_;
        dim3 gdd(D_ / 32, D_ / 32, L_);
        wtrans_kernel<<<gdd, 256>>>(wq, wqkvhp,          wqkvlp,          D_, D_, (size_t)D3 * D_);
        wtrans_kernel<<<gdd, 256>>>(wk, wqkvhp + DD,     wqkvlp + DD,     D_, D_, (size_t)D3 * D_);
        wtrans_kernel<<<gdd, 256>>>(wv, wqkvhp + 2 * DD, wqkvlp + 2 * DD, D_, D_, (size_t)D3 * D_);
        wtrans_kernel<<<gdd, 256>>>(wo, woh, wol, D_, D_, DD);
        dim3 g1(F_ / 32, D_ / 32, L_);
        wtrans_kernel<<<g1, 256>>>(w1, w1h, w1l, D_, F_, (size_t)D_ * F_);
        dim3 g2(D_ / 32, F_ / 32, L_);
        wtrans_kernel<<<g2, 256>>>(w2, w2h, w2l, F_, D_, (size_t)F_ * D_);
    }

    dim3 gQKV(D3 / 128, M_ / 128);   // (24, 64)
    dim3 gD(D_ / 128, M_ / 128);     // (8, 64)
    dim3 gF(F_ / 128, M_ / 128);     // (32, 64)
    dim3 gAttn(S_ / QT, H_, B_);

    for (int l = 0; l < L_; l++) {
        size_t oQKV = (size_t)l * D3 * D_;
        size_t oDD  = (size_t)l * D_ * D_;
        size_t oDF  = (size_t)l * D_ * F_;
        size_t oD   = (size_t)l * D_;
        size_t oF   = (size_t)l * F_;

        ln_kernel<<<M_, 256>>>(hb, ln1g + oD, ln1b + oD, xnh, xnl);
        gemm_mma_kernel<<<gQKV, 256, GEMM_SMEM>>>(xnh, xnl, wqkvhp + oQKV, wqkvlp + oQKV,
            bqkv + (size_t)l * D3, nullptr, nullptr, nullptr, qkvh, qkvl, D3, D_, 0);

        attn_mma_kernel<<<gAttn, 256, ATTN_SMEM>>>(qkvh, qkvl,
            bt + (size_t)l * (2 * P_ - 1) * H_, cxh, cxl);

        gemm_mma_kernel<<<gD, 256, GEMM_SMEM>>>(cxh, cxl, woh + oDD, wol + oDD,
            bo + oD, hb, nullptr, o1, nullptr, nullptr, D_, D_, 0);

        ln_kernel<<<M_, 256>>>(o1, ln2g + oD, ln2b + oD, xnh, xnl);
        gemm_mma_kernel<<<gF, 256, GEMM_SMEM>>>(xnh, xnl, w1h + oDF, w1l + oDF,
            b1 + oF, nullptr, nullptr, nullptr, f1h, f1l, F_, D_, 1);
        float* dst = (l == L_ - 1) ? out : hb;
        gemm_mma_kernel<<<gD, 256, GEMM_SMEM>>>(f1h, f1l, w2h + oDF, w2l + oDF,
            b2 + oD, o1, hb, dst, nullptr, nullptr, D_, F_, 0);
    }
}